// round 5
// baseline (speedup 1.0000x reference)
#include <cuda_runtime.h>

#define NN 200000
#define NE 2000000
#define BB 1024
#define SEQL 1000
#define NVOC 26
#define PAD 48
#define NBLK ((NN + 255) / 256)   // 782

// ---------------- scratch (static __device__, no allocs) ----------------
__device__ float g_h[NN * 32];
__device__ float g_h2[NN * 32];             // ping-pong partner (layer fusion needs distinct in/out)
__device__ float g_sum[32];
__device__ float g_ss[32];
__device__ float g_scale[32];
__device__ float g_shift[32];
__device__ float g_pooled[BB * 32];
__device__ float g_xc[BB * 256];
__device__ float g_t1[BB * 1024];
__device__ float g_t2[BB * 256];
__device__ float g_Wt[SEQL * 256];          // convW transposed: [c][(o,k)]
__device__ float g_G[256 * NVOC * 128];     // [(o*8+k)][v*128+j]
__device__ float g_H[SEQL * NVOC * 128];    // [(c*26+v)*128+j]
__device__ float g_cb[128];
__device__ int   g_deg[NN];                 // degree / fill cursor
__device__ int   g_colp[NN * PAD];          // padded adjacency
__device__ int   g_tT[SEQL * BB];           // transposed targets [c][b]
__device__ int   g_ctr;                     // colsum last-block counter

// ================= init: zero cursors, pooled, counter =================
__global__ __launch_bounds__(256) void zero_kernel() {
    int i = blockIdx.x * 256 + threadIdx.x;
    if (i < NN) g_deg[i] = 0;
    if (i < BB * 32) g_pooled[i] = 0.f;
    if (i == 0) g_ctr = 0;
}

// ================= padded adjacency fill =================
__global__ __launch_bounds__(256) void fill_kernel(const int* __restrict__ src,
                                                   const int* __restrict__ dst) {
    int e = blockIdx.x * 256 + threadIdx.x;
    if (e < NE) {
        int d = __ldg(dst + e);
        int slot = atomicAdd(&g_deg[d], 1);
        if (slot < PAD) g_colp[d * PAD + slot] = __ldg(src + e);
    }
}

// ---------------- layer-1 projection: z = x @ W1a ----------------
__global__ __launch_bounds__(256) void proj_kernel(const float* __restrict__ x,
                                                   const float* __restrict__ W,
                                                   float* __restrict__ h) {
    __shared__ float sW[78 * 32];
    int t = threadIdx.x;
    for (int i = t; i < 78 * 32; i += 256) sW[i] = W[i];
    __syncthreads();
    int node = blockIdx.x * 256 + t;
    if (node >= NN) return;
    float acc[32];
#pragma unroll
    for (int j = 0; j < 32; j++) acc[j] = 0.f;
    const float* xr = x + (long long)node * 78;
    for (int f = 0; f < 78; f++) {
        float xv = __ldg(xr + f);
#pragma unroll
        for (int j = 0; j < 32; j++) acc[j] += xv * sW[f * 32 + j];
    }
    float4* hp = (float4*)(h + node * 32);
#pragma unroll
    for (int q = 0; q < 8; q++)
        hp[q] = make_float4(acc[q * 4], acc[q * 4 + 1], acc[q * 4 + 2], acc[q * 4 + 3]);
}

// ---------------- fused layer: gather(+BN affine) -> smem -> 2x32x32 MLP ----------
// h_in and h_out MUST be distinct buffers (neighbor gather reads h_in globally).
__global__ __launch_bounds__(256) void layer_kernel(const float* __restrict__ h_in,
                                                    float* __restrict__ h_out,
                                                    const float* __restrict__ W1,
                                                    const float* __restrict__ b1,
                                                    const float* __restrict__ W2,
                                                    const float* __restrict__ b2,
                                                    int useNorm) {
    __shared__ float sA[256 * 33];
    __shared__ float sW1[1024], sW2[1024], sb1[32], sb2[32];
    int t = threadIdx.x;
    if (blockIdx.x == 0 && t < 64) {
        if (t < 32) g_sum[t] = 0.f;
        else g_ss[t - 32] = 0.f;
    }
    if (W1) { for (int i = t; i < 1024; i += 256) sW1[i] = W1[i]; }
    for (int i = t; i < 1024; i += 256) sW2[i] = W2[i];
    if (t < 32) { sb1[t] = b1[t]; sb2[t] = b2[t]; }

    int node0 = blockIdx.x * 256;
    // ---- Phase A: gather (8 threads per node) ----
#pragma unroll
    for (int r = 0; r < 8; r++) {
        int idx = r * 256 + t;
        int nl = idx >> 3, q = idx & 7;
        int node = node0 + nl;
        float4 acc = make_float4(0.f, 0.f, 0.f, 0.f);
        float cnt = 1.f;
        if (node < NN) {
            acc = __ldg((const float4*)(h_in + node * 32) + q);
            int deg = __ldg(&g_deg[node]);
            if (deg > PAD) deg = PAD;
            const int* cp = g_colp + node * PAD;
            int s = 0;
            for (; s + 1 < deg; s += 2) {
                int n1 = __ldg(cp + s), n2 = __ldg(cp + s + 1);
                float4 v1 = __ldg((const float4*)(h_in + n1 * 32) + q);
                float4 v2 = __ldg((const float4*)(h_in + n2 * 32) + q);
                acc.x += v1.x + v2.x; acc.y += v1.y + v2.y;
                acc.z += v1.z + v2.z; acc.w += v1.w + v2.w;
            }
            if (s < deg) {
                int n1 = __ldg(cp + s);
                float4 v1 = __ldg((const float4*)(h_in + n1 * 32) + q);
                acc.x += v1.x; acc.y += v1.y; acc.z += v1.z; acc.w += v1.w;
            }
            cnt = (float)(deg + 1);
        }
        if (useNorm) {
            float4 sc = ((const float4*)g_scale)[q];
            float4 sh = ((const float4*)g_shift)[q];
            acc.x = sc.x * acc.x + cnt * sh.x;
            acc.y = sc.y * acc.y + cnt * sh.y;
            acc.z = sc.z * acc.z + cnt * sh.z;
            acc.w = sc.w * acc.w + cnt * sh.w;
        }
        float* sp = sA + nl * 33 + q * 4;
        sp[0] = acc.x; sp[1] = acc.y; sp[2] = acc.z; sp[3] = acc.w;
    }
    __syncthreads();
    // ---- Phase B: MLP (1 thread per node) ----
    int node = node0 + t;
    if (node >= NN) return;
    float a[32];
#pragma unroll
    for (int j = 0; j < 32; j++) a[j] = sA[t * 33 + j];
    float t1[32];
    if (W1) {
#pragma unroll
        for (int j = 0; j < 32; j++) t1[j] = sb1[j];
#pragma unroll
        for (int f = 0; f < 32; f++) {
            float av = a[f];
#pragma unroll
            for (int j = 0; j < 32; j++) t1[j] += av * sW1[f * 32 + j];
        }
#pragma unroll
        for (int j = 0; j < 32; j++) t1[j] = fmaxf(t1[j], 0.f);
    } else {
#pragma unroll
        for (int j = 0; j < 32; j++) t1[j] = fmaxf(a[j] + sb1[j], 0.f);
    }
    float r[32];
#pragma unroll
    for (int j = 0; j < 32; j++) r[j] = sb2[j];
#pragma unroll
    for (int f = 0; f < 32; f++) {
        float tv = t1[f];
#pragma unroll
        for (int j = 0; j < 32; j++) r[j] += tv * sW2[f * 32 + j];
    }
    float4* hp = (float4*)(h_out + node * 32);
#pragma unroll
    for (int q = 0; q < 8; q++)
        hp[q] = make_float4(fmaxf(r[q * 4], 0.f), fmaxf(r[q * 4 + 1], 0.f),
                            fmaxf(r[q * 4 + 2], 0.f), fmaxf(r[q * 4 + 3], 0.f));
}

// ---------------- BN column sums + last-block finalize ----------------
__global__ __launch_bounds__(256) void colsum_fin_kernel(const float* __restrict__ h,
                                                         const float* __restrict__ gamma,
                                                         const float* __restrict__ beta) {
    __shared__ float rs[8][33], rss[8][33];
    __shared__ int isLast;
    int f = threadIdx.x & 31, sub = threadIdx.x >> 5;
    float s = 0.f, ss = 0.f;
    for (int row = blockIdx.x * 8 + sub; row < NN; row += gridDim.x * 8) {
        float v = __ldg(h + row * 32 + f);
        s += v; ss += v * v;
    }
    rs[sub][f] = s; rss[sub][f] = ss;
    __syncthreads();
    if (threadIdx.x < 32) {
        float a = 0.f, b = 0.f;
#pragma unroll
        for (int k = 0; k < 8; k++) { a += rs[k][f]; b += rss[k][f]; }
        atomicAdd(&g_sum[f], a);
        atomicAdd(&g_ss[f], b);
    }
    __threadfence();
    if (threadIdx.x == 0)
        isLast = (atomicAdd(&g_ctr, 1) == (int)gridDim.x - 1);
    __syncthreads();
    if (isLast) {
        if (threadIdx.x < 32) {
            int j = threadIdx.x;
            float m = g_sum[j] * (1.0f / (float)NN);
            float var = g_ss[j] * (1.0f / (float)NN) - m * m;
            float sc = __ldg(gamma + j) * rsqrtf(var + 1e-5f);
            g_scale[j] = sc;
            g_shift[j] = __ldg(beta + j) - m * sc;
        }
        if (threadIdx.x == 32) g_ctr = 0;
    }
}

// ---------------- pooling: pooled[batch[i]] += normalize(h[i]) ----------------
__global__ __launch_bounds__(256) void pool_kernel(const float* __restrict__ h,
                                                   const int* __restrict__ batch) {
    int node = blockIdx.x * 256 + threadIdx.x;
    if (node >= NN) return;
    int b = __ldg(batch + node);
    float* pr = g_pooled + b * 32;
    const float4* hp = (const float4*)(h + node * 32);
#pragma unroll
    for (int q = 0; q < 8; q++) {
        float4 v = hp[q];
        float4 sc = ((const float4*)g_scale)[q];
        float4 sh = ((const float4*)g_shift)[q];
        atomicAdd(pr + q * 4 + 0, v.x * sc.x + sh.x);
        atomicAdd(pr + q * 4 + 1, v.y * sc.y + sh.y);
        atomicAdd(pr + q * 4 + 2, v.z * sc.z + sh.z);
        atomicAdd(pr + q * 4 + 3, v.w * sc.w + sh.w);
    }
}

// ---------------- generic tiled GEMM ----------------
__global__ __launch_bounds__(256) void gemm64_kernel(const float* __restrict__ A,
                                                     const float* __restrict__ B,
                                                     const float* __restrict__ bias,
                                                     float* __restrict__ C,
                                                     int M, int N, int K, int ldc, int doRelu) {
    __shared__ float As[16][68];
    __shared__ float Bs[16][68];
    int tx = threadIdx.x & 15, ty = threadIdx.x >> 4;
    int m0 = blockIdx.y * 64, n0 = blockIdx.x * 64;
    int la_m = threadIdx.x >> 2;
    int la_k = (threadIdx.x & 3) * 4;
    int lb_k = threadIdx.x >> 4;
    int lb_n = (threadIdx.x & 15) * 4;
    float acc[4][4];
#pragma unroll
    for (int r = 0; r < 4; r++)
#pragma unroll
        for (int c = 0; c < 4; c++) acc[r][c] = 0.f;

    for (int k0 = 0; k0 < K; k0 += 16) {
        float4 av = make_float4(0.f, 0.f, 0.f, 0.f);
        if (m0 + la_m < M) av = *(const float4*)(A + (long long)(m0 + la_m) * K + k0 + la_k);
        As[la_k + 0][la_m] = av.x; As[la_k + 1][la_m] = av.y;
        As[la_k + 2][la_m] = av.z; As[la_k + 3][la_m] = av.w;
        float4 bv = *(const float4*)(B + (long long)(k0 + lb_k) * N + n0 + lb_n);
        *(float4*)&Bs[lb_k][lb_n] = bv;
        __syncthreads();
#pragma unroll
        for (int kk = 0; kk < 16; kk++) {
            float4 a4 = *(const float4*)&As[kk][ty * 4];
            float4 b4 = *(const float4*)&Bs[kk][tx * 4];
            acc[0][0] += a4.x * b4.x; acc[0][1] += a4.x * b4.y; acc[0][2] += a4.x * b4.z; acc[0][3] += a4.x * b4.w;
            acc[1][0] += a4.y * b4.x; acc[1][1] += a4.y * b4.y; acc[1][2] += a4.y * b4.z; acc[1][3] += a4.y * b4.w;
            acc[2][0] += a4.z * b4.x; acc[2][1] += a4.z * b4.y; acc[2][2] += a4.z * b4.z; acc[2][3] += a4.z * b4.w;
            acc[3][0] += a4.w * b4.x; acc[3][1] += a4.w * b4.y; acc[3][2] += a4.w * b4.z; acc[3][3] += a4.w * b4.w;
        }
        __syncthreads();
    }
#pragma unroll
    for (int r = 0; r < 4; r++) {
        int row = m0 + ty * 4 + r;
        if (row >= M) continue;
#pragma unroll
        for (int c = 0; c < 4; c++) {
            int col = n0 + tx * 4 + c;
            float v = acc[r][c];
            if (bias) v += __ldg(bias + col);
            if (doRelu) v = fmaxf(v, 0.f);
            C[(long long)row * ldc + col] = v;
        }
    }
}

// ---------------- protein branch precomputes ----------------
__global__ void wtrans_kernel(const float* __restrict__ convW) {
    int i = blockIdx.x * 256 + threadIdx.x;
    if (i < SEQL * 256) {
        int c = i >> 8, ok = i & 255, o = ok >> 3, k = ok & 7;
        g_Wt[i] = convW[o * 8000 + c * 8 + k];
    }
}

__global__ __launch_bounds__(1024) void g_kernel(const float* __restrict__ emb,
                                                 const float* __restrict__ Fw) {
    int o = blockIdx.x, v = blockIdx.y;
    int j = threadIdx.x, k = threadIdx.y;  // (128, 8)
    __shared__ float E[128];
    if (threadIdx.y == 0) E[j] = emb[v * 128 + j];
    __syncthreads();
    float acc = 0.f;
    const float* fp = Fw + (long long)(o * 121) * 128 + j;
#pragma unroll 11
    for (int l = 0; l < 121; l++) acc += E[l + k] * fp[l * 128];
    g_G[(o * 8 + k) * (NVOC * 128) + v * 128 + j] = acc;
}

__global__ void cb_kernel(const float* __restrict__ Fw, const float* __restrict__ convb,
                          const float* __restrict__ fcxt_b) {
    int j = threadIdx.x;
    float acc = fcxt_b[j];
    for (int o = 0; o < 32; o++) {
        float fs = 0.f;
        for (int l = 0; l < 121; l++) fs += Fw[(long long)(o * 121 + l) * 128 + j];
        acc += convb[o] * fs;
    }
    g_cb[j] = acc;
}

// init xt region of xc with cb (xt kernel accumulates on top)
__global__ __launch_bounds__(256) void cbinit_kernel() {
    int i = blockIdx.x * 256 + threadIdx.x;
    if (i < BB * 128) {
        int b = i >> 7, j = i & 127;
        g_xc[b * 256 + 128 + j] = g_cb[j];
    }
}

// target transpose: tT[c][b] = target[b][c]  (32x32 tiles)
__global__ __launch_bounds__(256) void ttrans_kernel(const int* __restrict__ target) {
    __shared__ int tile[32][33];
    int c0 = blockIdx.x * 32, b0 = blockIdx.y * 32;
    int tx = threadIdx.x & 31, ty = threadIdx.x >> 5;  // 32 x 8
#pragma unroll
    for (int r = 0; r < 4; r++) {
        int b = b0 + ty + r * 8;
        int c = c0 + tx;
        tile[ty + r * 8][tx] = (c < SEQL) ? __ldg(target + (long long)b * SEQL + c) : 0;
    }
    __syncthreads();
#pragma unroll
    for (int r = 0; r < 4; r++) {
        int c = c0 + ty + r * 8;
        int b = b0 + tx;
        if (c < SEQL) g_tT[c * BB + b] = tile[tx][ty + r * 8];
    }
}

// blocked xt: grid (8 j-chunks, 20 c-chunks), 512 threads
__global__ __launch_bounds__(512) void xt_kernel() {
    __shared__ float sH[NVOC * 16];
    __shared__ int tv[BB];
    int jc = blockIdx.x, cc = blockIdx.y;
    int t = threadIdx.x;
    int jl = t & 15, bg = t >> 4;
    float acc[32];
#pragma unroll
    for (int i = 0; i < 32; i++) acc[i] = 0.f;
    for (int c = cc * 50; c < cc * 50 + 50; c++) {
        if (t < NVOC * 16) {
            int v = t >> 4, jj = t & 15;
            sH[t] = g_H[((long long)c * NVOC + v) * 128 + jc * 16 + jj];
        }
        tv[t] = g_tT[c * BB + t];
        tv[t + 512] = g_tT[c * BB + t + 512];
        __syncthreads();
#pragma unroll
        for (int bi = 0; bi < 32; bi++) {
            int b = bi * 32 + bg;
            acc[bi] += sH[tv[b] * 16 + jl];
        }
        __syncthreads();
    }
#pragma unroll
    for (int bi = 0; bi < 32; bi++) {
        int b = bi * 32 + bg;
        atomicAdd(&g_xc[b * 256 + 128 + jc * 16 + jl], acc[bi]);
    }
}

__global__ void out_kernel(const float* __restrict__ W, const float* __restrict__ b,
                           float* __restrict__ out) {
    int row = blockIdx.x * 8 + (threadIdx.x >> 5);
    int lane = threadIdx.x & 31;
    if (row >= BB) return;
    float acc = 0.f;
    for (int i = lane; i < 256; i += 32) acc += g_t2[row * 256 + i] * __ldg(W + i);
#pragma unroll
    for (int off = 16; off; off >>= 1) acc += __shfl_down_sync(0xffffffffu, acc, off);
    if (lane == 0) out[row] = acc + __ldg(b);
}

// ---------------- launch ----------------
extern "C" void kernel_launch(void* const* d_in, const int* in_sizes, int n_in,
                              void* d_out, int out_size) {
    const float* x      = (const float*)d_in[0];
    const int*   ei     = (const int*)d_in[1];
    const int*   src    = ei;
    const int*   dst    = ei + NE;
    const int*   batch  = (const int*)d_in[2];
    const int*   target = (const int*)d_in[3];
    const float* W1a = (const float*)d_in[4];
    const float* b1a = (const float*)d_in[5];
    const float* W2a = (const float*)d_in[6];
    const float* b2a = (const float*)d_in[7];
    const float* g1  = (const float*)d_in[8];
    const float* be1 = (const float*)d_in[9];
    const float* Ws1 = (const float*)d_in[10];
    const float* bs1 = (const float*)d_in[11];
    const float* Ws2 = (const float*)d_in[12];
    const float* bs2 = (const float*)d_in[13];
    const float* gs  = (const float*)d_in[14];
    const float* bes = (const float*)d_in[15];
    const float* fc1xd_W = (const float*)d_in[16];
    const float* fc1xd_b = (const float*)d_in[17];
    const float* emb     = (const float*)d_in[18];
    const float* convW   = (const float*)d_in[19];
    const float* convb   = (const float*)d_in[20];
    const float* fcxt_W  = (const float*)d_in[21];
    const float* fcxt_b  = (const float*)d_in[22];
    const float* fc1_W   = (const float*)d_in[23];
    const float* fc1_b   = (const float*)d_in[24];
    const float* fc2_W   = (const float*)d_in[25];
    const float* fc2_b   = (const float*)d_in[26];
    const float* out_W   = (const float*)d_in[27];
    const float* out_b   = (const float*)d_in[28];

    float *p_h, *p_h2, *p_pooled, *p_xc, *p_t1, *p_t2, *p_Wt, *p_G, *p_H;
    cudaGetSymbolAddress((void**)&p_h, g_h);
    cudaGetSymbolAddress((void**)&p_h2, g_h2);
    cudaGetSymbolAddress((void**)&p_pooled, g_pooled);
    cudaGetSymbolAddress((void**)&p_xc, g_xc);
    cudaGetSymbolAddress((void**)&p_t1, g_t1);
    cudaGetSymbolAddress((void**)&p_t2, g_t2);
    cudaGetSymbolAddress((void**)&p_Wt, g_Wt);
    cudaGetSymbolAddress((void**)&p_G, g_G);
    cudaGetSymbolAddress((void**)&p_H, g_H);

    const int EDGE_BLOCKS = (NE + 255) / 256;       // 7813

    // adjacency build
    zero_kernel<<<NBLK, 256>>>();
    fill_kernel<<<EDGE_BLOCKS, 256>>>(src, dst);

    // layer-1 projection -> g_h
    proj_kernel<<<NBLK, 256>>>(x, W1a, p_h);

    // fused layer 1:  g_h -> g_h2   (ping-pong; in/out must differ)
    layer_kernel<<<NBLK, 256>>>(p_h, p_h2, nullptr, b1a, W2a, b2a, 0);
    colsum_fin_kernel<<<625, 256>>>(p_h2, g1, be1);

    // layers 2..5 alternate buffers: L2 h2->h, L3 h->h2, L4 h2->h, L5 h->h2
    float* bufs[2] = {p_h2, p_h};
    for (int i = 0; i < 4; i++) {
        float* in  = bufs[i & 1];
        float* out = bufs[(i + 1) & 1];
        layer_kernel<<<NBLK, 256>>>(in, out, Ws1 + i * 1024, bs1 + i * 32,
                                    Ws2 + i * 1024, bs2 + i * 32, 1);
        colsum_fin_kernel<<<625, 256>>>(out, gs + i * 32, bes + i * 32);
    }
    float* p_final = bufs[0];   // after 4 iterations output is back in p_h2

    // pooling + drug head
    pool_kernel<<<NBLK, 256>>>(p_final, batch);
    gemm64_kernel<<<dim3(128 / 64, BB / 64), 256>>>(p_pooled, fc1xd_W, fc1xd_b,
                                                    p_xc, BB, 128, 32, 256, 1);

    // protein branch
    wtrans_kernel<<<(SEQL * 256 + 255) / 256, 256>>>(convW);
    g_kernel<<<dim3(32, NVOC), dim3(128, 8)>>>(emb, fcxt_W);
    cb_kernel<<<1, 128>>>(fcxt_W, convb, fcxt_b);
    cbinit_kernel<<<(BB * 128 + 255) / 256, 256>>>();
    ttrans_kernel<<<dim3((SEQL + 31) / 32, BB / 32), 256>>>(target);
    gemm64_kernel<<<dim3((NVOC * 128) / 64, (SEQL + 63) / 64), 256>>>(
        p_Wt, p_G, nullptr, p_H, SEQL, NVOC * 128, 256, NVOC * 128, 0);
    xt_kernel<<<dim3(8, 20), 512>>>();

    // joint head
    gemm64_kernel<<<dim3(1024 / 64, BB / 64), 256>>>(p_xc, fc1_W, fc1_b, p_t1, BB, 1024, 256, 1024, 1);
    gemm64_kernel<<<dim3(256 / 64, BB / 64), 256>>>(p_t1, fc2_W, fc2_b, p_t2, BB, 256, 1024, 256, 1);
    out_kernel<<<BB / 8, 256>>>(out_W, out_b, (float*)d_out);
}

// round 6
// speedup vs baseline: 1.2051x; 1.2051x over previous
#include <cuda_runtime.h>

#define NN 200000
#define NE 2000000
#define BB 1024
#define SEQL 1000
#define NVOC 26
#define PAD 48
#define NBLK ((NN + 255) / 256)   // 782

// ---------------- scratch (static __device__, no allocs) ----------------
__device__ float g_h[NN * 32];
__device__ float g_agg[NN * 32];
__device__ float g_sum[32];
__device__ float g_ss[32];
__device__ float g_scale[32];
__device__ float g_shift[32];
__device__ float g_pooled[BB * 32];
__device__ float g_xc[BB * 256];
__device__ float g_t1[BB * 1024];
__device__ float g_t2[BB * 256];
__device__ float g_Wt[SEQL * 256];          // convW transposed: [c][(o,k)]
__device__ float g_G[256 * NVOC * 128];     // [(o*8+k)][v*128+j]
__device__ float g_H[SEQL * NVOC * 128];    // [(c*26+v)*128+j]
__device__ float g_cb[128];
__device__ int   g_deg[NN];                 // degree / fill cursor
__device__ int   g_colp[NN * PAD];          // padded adjacency
__device__ int   g_tT[SEQL * BB];           // transposed targets [c][b]
__device__ int   g_ctr;                     // colsum last-block counter

// ================= init: zero cursors, pooled, counter =================
__global__ __launch_bounds__(256) void zero_kernel() {
    int i = blockIdx.x * 256 + threadIdx.x;
    if (i < NN) g_deg[i] = 0;
    if (i < BB * 32) g_pooled[i] = 0.f;
    if (i == 0) g_ctr = 0;
}

// ================= padded adjacency fill =================
__global__ __launch_bounds__(256) void fill_kernel(const int* __restrict__ src,
                                                   const int* __restrict__ dst) {
    int e = blockIdx.x * 256 + threadIdx.x;
    if (e < NE) {
        int d = __ldg(dst + e);
        int slot = atomicAdd(&g_deg[d], 1);
        if (slot < PAD) g_colp[d * PAD + slot] = __ldg(src + e);
    }
}

// ---------------- layer-1 projection: z = x @ W1a ----------------
__global__ __launch_bounds__(256) void proj_kernel(const float* __restrict__ x,
                                                   const float* __restrict__ W,
                                                   float* __restrict__ h) {
    __shared__ float sW[78 * 32];
    int t = threadIdx.x;
    for (int i = t; i < 78 * 32; i += 256) sW[i] = W[i];
    __syncthreads();
    int node = blockIdx.x * 256 + t;
    if (node >= NN) return;
    float acc[32];
#pragma unroll
    for (int j = 0; j < 32; j++) acc[j] = 0.f;
    const float* xr = x + (long long)node * 78;
    for (int f = 0; f < 78; f++) {
        float xv = __ldg(xr + f);
#pragma unroll
        for (int j = 0; j < 32; j++) acc[j] += xv * sW[f * 32 + j];
    }
    float4* hp = (float4*)(h + node * 32);
#pragma unroll
    for (int q = 0; q < 8; q++)
        hp[q] = make_float4(acc[q * 4], acc[q * 4 + 1], acc[q * 4 + 2], acc[q * 4 + 3]);
}

// ---------------- gather aggregation (+ fused BN affine of previous layer) ---------
// 8 threads/node, no smem, low regs -> high occupancy to hide L2 latency.
// Also zeroes BN stat accumulators for the colsum that follows this layer.
__global__ __launch_bounds__(256) void agg_kernel(const float* __restrict__ h,
                                                  float* __restrict__ agg, int useNorm) {
    if (blockIdx.x == 0 && threadIdx.x < 64) {
        if (threadIdx.x < 32) g_sum[threadIdx.x] = 0.f;
        else g_ss[threadIdx.x - 32] = 0.f;
    }
    int gid = blockIdx.x * 256 + threadIdx.x;
    int node = gid >> 3, q = gid & 7;
    if (node >= NN) return;
    int deg = __ldg(&g_deg[node]);
    if (deg > PAD) deg = PAD;
    const int* cp = g_colp + node * PAD;
    float4 acc = __ldg((const float4*)(h + node * 32) + q);
    int s = 0;
    for (; s + 3 < deg; s += 4) {
        int n1 = __ldg(cp + s), n2 = __ldg(cp + s + 1);
        int n3 = __ldg(cp + s + 2), n4 = __ldg(cp + s + 3);
        float4 v1 = __ldg((const float4*)(h + n1 * 32) + q);
        float4 v2 = __ldg((const float4*)(h + n2 * 32) + q);
        float4 v3 = __ldg((const float4*)(h + n3 * 32) + q);
        float4 v4 = __ldg((const float4*)(h + n4 * 32) + q);
        acc.x += (v1.x + v2.x) + (v3.x + v4.x);
        acc.y += (v1.y + v2.y) + (v3.y + v4.y);
        acc.z += (v1.z + v2.z) + (v3.z + v4.z);
        acc.w += (v1.w + v2.w) + (v3.w + v4.w);
    }
    for (; s < deg; s++) {
        int n1 = __ldg(cp + s);
        float4 v1 = __ldg((const float4*)(h + n1 * 32) + q);
        acc.x += v1.x; acc.y += v1.y; acc.z += v1.z; acc.w += v1.w;
    }
    if (useNorm) {
        float4 sc = ((const float4*)g_scale)[q];
        float4 sh = ((const float4*)g_shift)[q];
        float cnt = (float)(deg + 1);
        acc.x = sc.x * acc.x + cnt * sh.x;
        acc.y = sc.y * acc.y + cnt * sh.y;
        acc.z = sc.z * acc.z + cnt * sh.z;
        acc.w = sc.w * acc.w + cnt * sh.w;
    }
    ((float4*)(agg + node * 32))[q] = acc;
}

// ---------------- per-node GIN MLP + relu ----------------
__global__ __launch_bounds__(256) void nodepass_kernel(const float* __restrict__ agg,
                                                       float* __restrict__ hout,
                                                       const float* __restrict__ W1,
                                                       const float* __restrict__ b1,
                                                       const float* __restrict__ W2,
                                                       const float* __restrict__ b2) {
    __shared__ float sW1[1024], sW2[1024], sb1[32], sb2[32];
    int t = threadIdx.x;
    if (W1) { for (int i = t; i < 1024; i += 256) sW1[i] = W1[i]; }
    for (int i = t; i < 1024; i += 256) sW2[i] = W2[i];
    if (t < 32) { sb1[t] = b1[t]; sb2[t] = b2[t]; }
    __syncthreads();
    int node = blockIdx.x * 256 + t;
    if (node >= NN) return;
    float a[32];
    const float4* ap = (const float4*)(agg + node * 32);
#pragma unroll
    for (int q = 0; q < 8; q++) {
        float4 v = ap[q];
        a[q * 4] = v.x; a[q * 4 + 1] = v.y; a[q * 4 + 2] = v.z; a[q * 4 + 3] = v.w;
    }
    float t1[32];
    if (W1) {
#pragma unroll
        for (int j = 0; j < 32; j++) t1[j] = sb1[j];
#pragma unroll
        for (int f = 0; f < 32; f++) {
            float av = a[f];
#pragma unroll
            for (int j = 0; j < 32; j++) t1[j] += av * sW1[f * 32 + j];
        }
#pragma unroll
        for (int j = 0; j < 32; j++) t1[j] = fmaxf(t1[j], 0.f);
    } else {
#pragma unroll
        for (int j = 0; j < 32; j++) t1[j] = fmaxf(a[j] + sb1[j], 0.f);
    }
    float r[32];
#pragma unroll
    for (int j = 0; j < 32; j++) r[j] = sb2[j];
#pragma unroll
    for (int f = 0; f < 32; f++) {
        float tv = t1[f];
#pragma unroll
        for (int j = 0; j < 32; j++) r[j] += tv * sW2[f * 32 + j];
    }
    float4* hp = (float4*)(hout + node * 32);
#pragma unroll
    for (int q = 0; q < 8; q++)
        hp[q] = make_float4(fmaxf(r[q * 4], 0.f), fmaxf(r[q * 4 + 1], 0.f),
                            fmaxf(r[q * 4 + 2], 0.f), fmaxf(r[q * 4 + 3], 0.f));
}

// ---------------- BN column sums + last-block finalize ----------------
__global__ __launch_bounds__(256) void colsum_fin_kernel(const float* __restrict__ h,
                                                         const float* __restrict__ gamma,
                                                         const float* __restrict__ beta) {
    __shared__ float rs[8][33], rss[8][33];
    __shared__ int isLast;
    int f = threadIdx.x & 31, sub = threadIdx.x >> 5;
    float s = 0.f, ss = 0.f;
    for (int row = blockIdx.x * 8 + sub; row < NN; row += gridDim.x * 8) {
        float v = __ldg(h + row * 32 + f);
        s += v; ss += v * v;
    }
    rs[sub][f] = s; rss[sub][f] = ss;
    __syncthreads();
    if (threadIdx.x < 32) {
        float a = 0.f, b = 0.f;
#pragma unroll
        for (int k = 0; k < 8; k++) { a += rs[k][f]; b += rss[k][f]; }
        atomicAdd(&g_sum[f], a);
        atomicAdd(&g_ss[f], b);
    }
    __threadfence();
    if (threadIdx.x == 0)
        isLast = (atomicAdd(&g_ctr, 1) == (int)gridDim.x - 1);
    __syncthreads();
    if (isLast) {
        if (threadIdx.x < 32) {
            int j = threadIdx.x;
            float m = g_sum[j] * (1.0f / (float)NN);
            float var = g_ss[j] * (1.0f / (float)NN) - m * m;
            float sc = __ldg(gamma + j) * rsqrtf(var + 1e-5f);
            g_scale[j] = sc;
            g_shift[j] = __ldg(beta + j) - m * sc;
        }
        if (threadIdx.x == 32) g_ctr = 0;
    }
}

// ---------------- pooling: pooled[batch[i]] += normalize(h[i]) ----------------
__global__ __launch_bounds__(256) void pool_kernel(const float* __restrict__ h,
                                                   const int* __restrict__ batch) {
    int node = blockIdx.x * 256 + threadIdx.x;
    if (node >= NN) return;
    int b = __ldg(batch + node);
    float* pr = g_pooled + b * 32;
    const float4* hp = (const float4*)(h + node * 32);
#pragma unroll
    for (int q = 0; q < 8; q++) {
        float4 v = hp[q];
        float4 sc = ((const float4*)g_scale)[q];
        float4 sh = ((const float4*)g_shift)[q];
        atomicAdd(pr + q * 4 + 0, v.x * sc.x + sh.x);
        atomicAdd(pr + q * 4 + 1, v.y * sc.y + sh.y);
        atomicAdd(pr + q * 4 + 2, v.z * sc.z + sh.z);
        atomicAdd(pr + q * 4 + 3, v.w * sc.w + sh.w);
    }
}

// ---------------- generic tiled GEMM ----------------
__global__ __launch_bounds__(256) void gemm64_kernel(const float* __restrict__ A,
                                                     const float* __restrict__ B,
                                                     const float* __restrict__ bias,
                                                     float* __restrict__ C,
                                                     int M, int N, int K, int ldc, int doRelu) {
    __shared__ float As[16][68];
    __shared__ float Bs[16][68];
    int tx = threadIdx.x & 15, ty = threadIdx.x >> 4;
    int m0 = blockIdx.y * 64, n0 = blockIdx.x * 64;
    int la_m = threadIdx.x >> 2;
    int la_k = (threadIdx.x & 3) * 4;
    int lb_k = threadIdx.x >> 4;
    int lb_n = (threadIdx.x & 15) * 4;
    float acc[4][4];
#pragma unroll
    for (int r = 0; r < 4; r++)
#pragma unroll
        for (int c = 0; c < 4; c++) acc[r][c] = 0.f;

    for (int k0 = 0; k0 < K; k0 += 16) {
        float4 av = make_float4(0.f, 0.f, 0.f, 0.f);
        if (m0 + la_m < M) av = *(const float4*)(A + (long long)(m0 + la_m) * K + k0 + la_k);
        As[la_k + 0][la_m] = av.x; As[la_k + 1][la_m] = av.y;
        As[la_k + 2][la_m] = av.z; As[la_k + 3][la_m] = av.w;
        float4 bv = *(const float4*)(B + (long long)(k0 + lb_k) * N + n0 + lb_n);
        *(float4*)&Bs[lb_k][lb_n] = bv;
        __syncthreads();
#pragma unroll
        for (int kk = 0; kk < 16; kk++) {
            float4 a4 = *(const float4*)&As[kk][ty * 4];
            float4 b4 = *(const float4*)&Bs[kk][tx * 4];
            acc[0][0] += a4.x * b4.x; acc[0][1] += a4.x * b4.y; acc[0][2] += a4.x * b4.z; acc[0][3] += a4.x * b4.w;
            acc[1][0] += a4.y * b4.x; acc[1][1] += a4.y * b4.y; acc[1][2] += a4.y * b4.z; acc[1][3] += a4.y * b4.w;
            acc[2][0] += a4.z * b4.x; acc[2][1] += a4.z * b4.y; acc[2][2] += a4.z * b4.z; acc[2][3] += a4.z * b4.w;
            acc[3][0] += a4.w * b4.x; acc[3][1] += a4.w * b4.y; acc[3][2] += a4.w * b4.z; acc[3][3] += a4.w * b4.w;
        }
        __syncthreads();
    }
#pragma unroll
    for (int r = 0; r < 4; r++) {
        int row = m0 + ty * 4 + r;
        if (row >= M) continue;
#pragma unroll
        for (int c = 0; c < 4; c++) {
            int col = n0 + tx * 4 + c;
            float v = acc[r][c];
            if (bias) v += __ldg(bias + col);
            if (doRelu) v = fmaxf(v, 0.f);
            C[(long long)row * ldc + col] = v;
        }
    }
}

// ---------------- protein branch precomputes ----------------
__global__ void wtrans_kernel(const float* __restrict__ convW) {
    int i = blockIdx.x * 256 + threadIdx.x;
    if (i < SEQL * 256) {
        int c = i >> 8, ok = i & 255, o = ok >> 3, k = ok & 7;
        g_Wt[i] = convW[o * 8000 + c * 8 + k];
    }
}

__global__ __launch_bounds__(1024) void g_kernel(const float* __restrict__ emb,
                                                 const float* __restrict__ Fw) {
    int o = blockIdx.x, v = blockIdx.y;
    int j = threadIdx.x, k = threadIdx.y;  // (128, 8)
    __shared__ float E[128];
    if (threadIdx.y == 0) E[j] = emb[v * 128 + j];
    __syncthreads();
    float acc = 0.f;
    const float* fp = Fw + (long long)(o * 121) * 128 + j;
#pragma unroll 11
    for (int l = 0; l < 121; l++) acc += E[l + k] * fp[l * 128];
    g_G[(o * 8 + k) * (NVOC * 128) + v * 128 + j] = acc;
}

__global__ void cb_kernel(const float* __restrict__ Fw, const float* __restrict__ convb,
                          const float* __restrict__ fcxt_b) {
    int j = threadIdx.x;
    float acc = fcxt_b[j];
    for (int o = 0; o < 32; o++) {
        float fs = 0.f;
        for (int l = 0; l < 121; l++) fs += Fw[(long long)(o * 121 + l) * 128 + j];
        acc += convb[o] * fs;
    }
    g_cb[j] = acc;
}

// init xt region of xc with cb (xt kernel accumulates on top)
__global__ __launch_bounds__(256) void cbinit_kernel() {
    int i = blockIdx.x * 256 + threadIdx.x;
    if (i < BB * 128) {
        int b = i >> 7, j = i & 127;
        g_xc[b * 256 + 128 + j] = g_cb[j];
    }
}

// target transpose: tT[c][b] = target[b][c]  (32x32 tiles)
__global__ __launch_bounds__(256) void ttrans_kernel(const int* __restrict__ target) {
    __shared__ int tile[32][33];
    int c0 = blockIdx.x * 32, b0 = blockIdx.y * 32;
    int tx = threadIdx.x & 31, ty = threadIdx.x >> 5;  // 32 x 8
#pragma unroll
    for (int r = 0; r < 4; r++) {
        int b = b0 + ty + r * 8;
        int c = c0 + tx;
        tile[ty + r * 8][tx] = (c < SEQL) ? __ldg(target + (long long)b * SEQL + c) : 0;
    }
    __syncthreads();
#pragma unroll
    for (int r = 0; r < 4; r++) {
        int c = c0 + ty + r * 8;
        int b = b0 + tx;
        if (c < SEQL) g_tT[c * BB + b] = tile[tx][ty + r * 8];
    }
}

// blocked xt: grid (8 j-chunks, 20 c-chunks), 512 threads
__global__ __launch_bounds__(512) void xt_kernel() {
    __shared__ float sH[NVOC * 16];
    __shared__ int tv[BB];
    int jc = blockIdx.x, cc = blockIdx.y;
    int t = threadIdx.x;
    int jl = t & 15, bg = t >> 4;
    float acc[32];
#pragma unroll
    for (int i = 0; i < 32; i++) acc[i] = 0.f;
    for (int c = cc * 50; c < cc * 50 + 50; c++) {
        if (t < NVOC * 16) {
            int v = t >> 4, jj = t & 15;
            sH[t] = g_H[((long long)c * NVOC + v) * 128 + jc * 16 + jj];
        }
        tv[t] = g_tT[c * BB + t];
        tv[t + 512] = g_tT[c * BB + t + 512];
        __syncthreads();
#pragma unroll
        for (int bi = 0; bi < 32; bi++) {
            int b = bi * 32 + bg;
            acc[bi] += sH[tv[b] * 16 + jl];
        }
        __syncthreads();
    }
#pragma unroll
    for (int bi = 0; bi < 32; bi++) {
        int b = bi * 32 + bg;
        atomicAdd(&g_xc[b * 256 + 128 + jc * 16 + jl], acc[bi]);
    }
}

__global__ void out_kernel(const float* __restrict__ W, const float* __restrict__ b,
                           float* __restrict__ out) {
    int row = blockIdx.x * 8 + (threadIdx.x >> 5);
    int lane = threadIdx.x & 31;
    if (row >= BB) return;
    float acc = 0.f;
    for (int i = lane; i < 256; i += 32) acc += g_t2[row * 256 + i] * __ldg(W + i);
#pragma unroll
    for (int off = 16; off; off >>= 1) acc += __shfl_down_sync(0xffffffffu, acc, off);
    if (lane == 0) out[row] = acc + __ldg(b);
}

// ---------------- launch ----------------
extern "C" void kernel_launch(void* const* d_in, const int* in_sizes, int n_in,
                              void* d_out, int out_size) {
    const float* x      = (const float*)d_in[0];
    const int*   ei     = (const int*)d_in[1];
    const int*   src    = ei;
    const int*   dst    = ei + NE;
    const int*   batch  = (const int*)d_in[2];
    const int*   target = (const int*)d_in[3];
    const float* W1a = (const float*)d_in[4];
    const float* b1a = (const float*)d_in[5];
    const float* W2a = (const float*)d_in[6];
    const float* b2a = (const float*)d_in[7];
    const float* g1  = (const float*)d_in[8];
    const float* be1 = (const float*)d_in[9];
    const float* Ws1 = (const float*)d_in[10];
    const float* bs1 = (const float*)d_in[11];
    const float* Ws2 = (const float*)d_in[12];
    const float* bs2 = (const float*)d_in[13];
    const float* gs  = (const float*)d_in[14];
    const float* bes = (const float*)d_in[15];
    const float* fc1xd_W = (const float*)d_in[16];
    const float* fc1xd_b = (const float*)d_in[17];
    const float* emb     = (const float*)d_in[18];
    const float* convW   = (const float*)d_in[19];
    const float* convb   = (const float*)d_in[20];
    const float* fcxt_W  = (const float*)d_in[21];
    const float* fcxt_b  = (const float*)d_in[22];
    const float* fc1_W   = (const float*)d_in[23];
    const float* fc1_b   = (const float*)d_in[24];
    const float* fc2_W   = (const float*)d_in[25];
    const float* fc2_b   = (const float*)d_in[26];
    const float* out_W   = (const float*)d_in[27];
    const float* out_b   = (const float*)d_in[28];

    float *p_h, *p_agg, *p_pooled, *p_xc, *p_t1, *p_t2, *p_Wt, *p_G, *p_H;
    cudaGetSymbolAddress((void**)&p_h, g_h);
    cudaGetSymbolAddress((void**)&p_agg, g_agg);
    cudaGetSymbolAddress((void**)&p_pooled, g_pooled);
    cudaGetSymbolAddress((void**)&p_xc, g_xc);
    cudaGetSymbolAddress((void**)&p_t1, g_t1);
    cudaGetSymbolAddress((void**)&p_t2, g_t2);
    cudaGetSymbolAddress((void**)&p_Wt, g_Wt);
    cudaGetSymbolAddress((void**)&p_G, g_G);
    cudaGetSymbolAddress((void**)&p_H, g_H);

    const int EDGE_BLOCKS = (NE + 255) / 256;       // 7813
    const int AGG_BLOCKS  = (NN * 8 + 255) / 256;   // 6250

    // adjacency build
    zero_kernel<<<NBLK, 256>>>();
    fill_kernel<<<EDGE_BLOCKS, 256>>>(src, dst);

    // layer-1 projection -> g_h
    proj_kernel<<<NBLK, 256>>>(x, W1a, p_h);

    // layer 1: agg (no norm) -> nodepass -> colsum+finalize
    agg_kernel<<<AGG_BLOCKS, 256>>>(p_h, p_agg, 0);
    nodepass_kernel<<<NBLK, 256>>>(p_agg, p_h, nullptr, b1a, W2a, b2a);
    colsum_fin_kernel<<<625, 256>>>(p_h, g1, be1);

    // layers 2..5 (BN affine fused into agg)
    for (int i = 0; i < 4; i++) {
        agg_kernel<<<AGG_BLOCKS, 256>>>(p_h, p_agg, 1);
        nodepass_kernel<<<NBLK, 256>>>(p_agg, p_h, Ws1 + i * 1024, bs1 + i * 32,
                                       Ws2 + i * 1024, bs2 + i * 32);
        colsum_fin_kernel<<<625, 256>>>(p_h, gs + i * 32, bes + i * 32);
    }

    // pooling + drug head
    pool_kernel<<<NBLK, 256>>>(p_h, batch);
    gemm64_kernel<<<dim3(128 / 64, BB / 64), 256>>>(p_pooled, fc1xd_W, fc1xd_b,
                                                    p_xc, BB, 128, 32, 256, 1);

    // protein branch
    wtrans_kernel<<<(SEQL * 256 + 255) / 256, 256>>>(convW);
    g_kernel<<<dim3(32, NVOC), dim3(128, 8)>>>(emb, fcxt_W);
    cb_kernel<<<1, 128>>>(fcxt_W, convb, fcxt_b);
    cbinit_kernel<<<(BB * 128 + 255) / 256, 256>>>();
    ttrans_kernel<<<dim3((SEQL + 31) / 32, BB / 32), 256>>>(target);
    gemm64_kernel<<<dim3((NVOC * 128) / 64, (SEQL + 63) / 64), 256>>>(
        p_Wt, p_G, nullptr, p_H, SEQL, NVOC * 128, 256, NVOC * 128, 0);
    xt_kernel<<<dim3(8, 20), 512>>>();

    // joint head
    gemm64_kernel<<<dim3(1024 / 64, BB / 64), 256>>>(p_xc, fc1_W, fc1_b, p_t1, BB, 1024, 256, 1024, 1);
    gemm64_kernel<<<dim3(256 / 64, BB / 64), 256>>>(p_t1, fc2_W, fc2_b, p_t2, BB, 256, 1024, 256, 1);
    out_kernel<<<BB / 8, 256>>>(out_W, out_b, (float*)d_out);
}

// round 7
// speedup vs baseline: 1.2830x; 1.0647x over previous
#include <cuda_runtime.h>

#define NN 200000
#define NE 2000000
#define BB 1024
#define SEQL 1000
#define NVOC 26
#define PAD 48
#define NBLK ((NN + 255) / 256)   // 782

typedef unsigned long long u64;
__device__ __forceinline__ u64 packf2(float lo, float hi) {
    u64 d; asm("mov.b64 %0, {%1,%2};" : "=l"(d) : "f"(lo), "f"(hi)); return d;
}
__device__ __forceinline__ void unpackf2(u64 s, float& lo, float& hi) {
    asm("mov.b64 {%0,%1}, %2;" : "=f"(lo), "=f"(hi) : "l"(s));
}
__device__ __forceinline__ u64 fmaf2(u64 a, u64 b, u64 c) {
    u64 d; asm("fma.rn.f32x2 %0, %1, %2, %3;" : "=l"(d) : "l"(a), "l"(b), "l"(c)); return d;
}
__device__ __forceinline__ u64 addf2(u64 a, u64 b) {
    u64 d; asm("add.rn.f32x2 %0, %1, %2;" : "=l"(d) : "l"(a), "l"(b)); return d;
}

// ---------------- scratch (static __device__, no allocs) ----------------
__device__ float g_h[NN * 32];
__device__ float g_agg[NN * 32];
__device__ float g_sum[32];
__device__ float g_ss[32];
__device__ float g_scale[32];
__device__ float g_shift[32];
__device__ float g_pooled[BB * 32];
__device__ float g_xc[BB * 256];
__device__ float g_t1[BB * 1024];
__device__ float g_t2[BB * 256];
__device__ float g_Wt[SEQL * 256];          // convW transposed: [c][(o,k)]
__device__ float g_G[256 * NVOC * 128];     // [(o*8+k)][v*128+j]
__device__ float g_H[SEQL * NVOC * 128];    // [(c*26+v)*128+j]
__device__ float g_cb[128];
__device__ int   g_deg[NN];
__device__ int   g_colp[NN * PAD];
__device__ int   g_tT[SEQL * BB];
__device__ int   g_ctr;

// ================= init =================
__global__ __launch_bounds__(256) void zero_kernel() {
    int i = blockIdx.x * 256 + threadIdx.x;
    if (i < NN) g_deg[i] = 0;
    if (i < BB * 32) g_pooled[i] = 0.f;
    if (i == 0) g_ctr = 0;
}

__global__ __launch_bounds__(256) void fill_kernel(const int* __restrict__ src,
                                                   const int* __restrict__ dst) {
    int e = blockIdx.x * 256 + threadIdx.x;
    if (e < NE) {
        int d = __ldg(dst + e);
        int slot = atomicAdd(&g_deg[d], 1);
        if (slot < PAD) g_colp[d * PAD + slot] = __ldg(src + e);
    }
}

// ---------------- layer-1 projection: z = x @ W1a (tiled, coalesced, f32x2) --------
#define PM 96
#define PSTR 98
__global__ __launch_bounds__(192) void proj_kernel(const float* __restrict__ x,
                                                   const float* __restrict__ W,
                                                   float* __restrict__ h) {
    __shared__ float sX[78 * PSTR];   // transposed [f][m]
    __shared__ float sW[78 * 32];
    int t = threadIdx.x;
    for (int i = t; i < 78 * 32; i += 192) sW[i] = W[i];
    long long node0 = (long long)blockIdx.x * PM;
    for (int i = t; i < PM * 78; i += 192) {
        int m = i / 78, f = i - m * 78;
        float v = (node0 + m < NN) ? x[node0 * 78 + i] : 0.f;
        sX[f * PSTR + m] = v;
    }
    __syncthreads();
    int jg = t & 7, mg = t >> 3;      // 8 x 24
    int m0 = mg * 4, j0 = jg * 4;
    u64 acc[2][4];
#pragma unroll
    for (int c = 0; c < 4; c++) { acc[0][c] = 0ull; acc[1][c] = 0ull; }
#pragma unroll 2
    for (int f = 0; f < 78; f++) {
        float4 w4 = *(const float4*)&sW[f * 32 + j0];
        u64 a0 = *(const u64*)&sX[f * PSTR + m0];
        u64 a1 = *(const u64*)&sX[f * PSTR + m0 + 2];
        u64 w;
        w = packf2(w4.x, w4.x); acc[0][0] = fmaf2(a0, w, acc[0][0]); acc[1][0] = fmaf2(a1, w, acc[1][0]);
        w = packf2(w4.y, w4.y); acc[0][1] = fmaf2(a0, w, acc[0][1]); acc[1][1] = fmaf2(a1, w, acc[1][1]);
        w = packf2(w4.z, w4.z); acc[0][2] = fmaf2(a0, w, acc[0][2]); acc[1][2] = fmaf2(a1, w, acc[1][2]);
        w = packf2(w4.w, w4.w); acc[0][3] = fmaf2(a0, w, acc[0][3]); acc[1][3] = fmaf2(a1, w, acc[1][3]);
    }
    float v[4][4];
#pragma unroll
    for (int c = 0; c < 4; c++) {
        unpackf2(acc[0][c], v[0][c], v[1][c]);
        unpackf2(acc[1][c], v[2][c], v[3][c]);
    }
#pragma unroll
    for (int i = 0; i < 4; i++) {
        if (node0 + m0 + i < NN)
            *(float4*)&h[(node0 + m0 + i) * 32 + j0] =
                make_float4(v[i][0], v[i][1], v[i][2], v[i][3]);
    }
}

// ---------------- gather aggregation (+ fused BN affine) ----------------
__global__ __launch_bounds__(256) void agg_kernel(const float* __restrict__ h,
                                                  float* __restrict__ agg, int useNorm) {
    if (blockIdx.x == 0 && threadIdx.x < 64) {
        if (threadIdx.x < 32) g_sum[threadIdx.x] = 0.f;
        else g_ss[threadIdx.x - 32] = 0.f;
    }
    int gid = blockIdx.x * 256 + threadIdx.x;
    int node = gid >> 3, q = gid & 7;
    if (node >= NN) return;
    int deg = __ldg(&g_deg[node]);
    if (deg > PAD) deg = PAD;
    const int* cp = g_colp + node * PAD;
    float4 acc = __ldg((const float4*)(h + node * 32) + q);
    int s = 0;
    for (; s + 3 < deg; s += 4) {
        int n1 = __ldg(cp + s), n2 = __ldg(cp + s + 1);
        int n3 = __ldg(cp + s + 2), n4 = __ldg(cp + s + 3);
        float4 v1 = __ldg((const float4*)(h + n1 * 32) + q);
        float4 v2 = __ldg((const float4*)(h + n2 * 32) + q);
        float4 v3 = __ldg((const float4*)(h + n3 * 32) + q);
        float4 v4 = __ldg((const float4*)(h + n4 * 32) + q);
        acc.x += (v1.x + v2.x) + (v3.x + v4.x);
        acc.y += (v1.y + v2.y) + (v3.y + v4.y);
        acc.z += (v1.z + v2.z) + (v3.z + v4.z);
        acc.w += (v1.w + v2.w) + (v3.w + v4.w);
    }
    for (; s < deg; s++) {
        int n1 = __ldg(cp + s);
        float4 v1 = __ldg((const float4*)(h + n1 * 32) + q);
        acc.x += v1.x; acc.y += v1.y; acc.z += v1.z; acc.w += v1.w;
    }
    if (useNorm) {
        float4 sc = ((const float4*)g_scale)[q];
        float4 sh = ((const float4*)g_shift)[q];
        float cnt = (float)(deg + 1);
        acc.x = sc.x * acc.x + cnt * sh.x;
        acc.y = sc.y * acc.y + cnt * sh.y;
        acc.z = sc.z * acc.z + cnt * sh.z;
        acc.w = sc.w * acc.w + cnt * sh.w;
    }
    ((float4*)(agg + node * 32))[q] = acc;
}

// ---------------- per-node GIN MLP + relu (register-blocked, f32x2) ----------------
// 256 threads, 128 nodes/block. W1==nullptr -> identity (layer 1: matmul folded in proj).
__global__ __launch_bounds__(256) void nodepass_kernel(const float* __restrict__ agg,
                                                       float* __restrict__ hout,
                                                       const float* __restrict__ W1,
                                                       const float* __restrict__ b1,
                                                       const float* __restrict__ W2,
                                                       const float* __restrict__ b2) {
    __shared__ float sT[32 * 130];    // transposed activations [f][m]
    __shared__ float sW1[1024], sW2[1024], sb1[32], sb2[32];
    int t = threadIdx.x;
    if (W1) { for (int i = t; i < 1024; i += 256) sW1[i] = W1[i]; }
    else    { for (int i = t; i < 1024; i += 256) sW1[i] = ((i >> 5) == (i & 31)) ? 1.f : 0.f; }
    for (int i = t; i < 1024; i += 256) sW2[i] = W2[i];
    if (t < 32) { sb1[t] = b1[t]; sb2[t] = b2[t]; }
    long long node0 = (long long)blockIdx.x * 128;
#pragma unroll
    for (int r = 0; r < 4; r++) {
        int fidx = r * 1024 + t * 4;
        int m = fidx >> 5, f = fidx & 31;
        float4 v = make_float4(0.f, 0.f, 0.f, 0.f);
        if (node0 + m < NN) v = *(const float4*)(agg + (node0 + m) * 32 + f);
        sT[f * 130 + m] = v.x; sT[(f + 1) * 130 + m] = v.y;
        sT[(f + 2) * 130 + m] = v.z; sT[(f + 3) * 130 + m] = v.w;
    }
    __syncthreads();
    int jg = t & 7, mg = t >> 3;
    int m0 = mg * 4, j0 = jg * 4;
    u64 acc[2][4];
#pragma unroll
    for (int c = 0; c < 4; c++) { float bb = sb1[j0 + c]; acc[0][c] = packf2(bb, bb); acc[1][c] = acc[0][c]; }
#pragma unroll
    for (int f = 0; f < 32; f++) {
        float4 w4 = *(const float4*)&sW1[f * 32 + j0];
        u64 a0 = *(const u64*)&sT[f * 130 + m0];
        u64 a1 = *(const u64*)&sT[f * 130 + m0 + 2];
        u64 w;
        w = packf2(w4.x, w4.x); acc[0][0] = fmaf2(a0, w, acc[0][0]); acc[1][0] = fmaf2(a1, w, acc[1][0]);
        w = packf2(w4.y, w4.y); acc[0][1] = fmaf2(a0, w, acc[0][1]); acc[1][1] = fmaf2(a1, w, acc[1][1]);
        w = packf2(w4.z, w4.z); acc[0][2] = fmaf2(a0, w, acc[0][2]); acc[1][2] = fmaf2(a1, w, acc[1][2]);
        w = packf2(w4.w, w4.w); acc[0][3] = fmaf2(a0, w, acc[0][3]); acc[1][3] = fmaf2(a1, w, acc[1][3]);
    }
    __syncthreads();   // everyone done reading sT
#pragma unroll
    for (int c = 0; c < 4; c++) {
        float x0, x1, x2, x3;
        unpackf2(acc[0][c], x0, x1); unpackf2(acc[1][c], x2, x3);
        x0 = fmaxf(x0, 0.f); x1 = fmaxf(x1, 0.f); x2 = fmaxf(x2, 0.f); x3 = fmaxf(x3, 0.f);
        *(u64*)&sT[(j0 + c) * 130 + m0]     = packf2(x0, x1);
        *(u64*)&sT[(j0 + c) * 130 + m0 + 2] = packf2(x2, x3);
    }
    __syncthreads();
#pragma unroll
    for (int c = 0; c < 4; c++) { float bb = sb2[j0 + c]; acc[0][c] = packf2(bb, bb); acc[1][c] = acc[0][c]; }
#pragma unroll
    for (int f = 0; f < 32; f++) {
        float4 w4 = *(const float4*)&sW2[f * 32 + j0];
        u64 a0 = *(const u64*)&sT[f * 130 + m0];
        u64 a1 = *(const u64*)&sT[f * 130 + m0 + 2];
        u64 w;
        w = packf2(w4.x, w4.x); acc[0][0] = fmaf2(a0, w, acc[0][0]); acc[1][0] = fmaf2(a1, w, acc[1][0]);
        w = packf2(w4.y, w4.y); acc[0][1] = fmaf2(a0, w, acc[0][1]); acc[1][1] = fmaf2(a1, w, acc[1][1]);
        w = packf2(w4.z, w4.z); acc[0][2] = fmaf2(a0, w, acc[0][2]); acc[1][2] = fmaf2(a1, w, acc[1][2]);
        w = packf2(w4.w, w4.w); acc[0][3] = fmaf2(a0, w, acc[0][3]); acc[1][3] = fmaf2(a1, w, acc[1][3]);
    }
    float v[4][4];
#pragma unroll
    for (int c = 0; c < 4; c++) {
        unpackf2(acc[0][c], v[0][c], v[1][c]);
        unpackf2(acc[1][c], v[2][c], v[3][c]);
    }
#pragma unroll
    for (int i = 0; i < 4; i++) {
        if (node0 + m0 + i < NN)
            *(float4*)&hout[(node0 + m0 + i) * 32 + j0] =
                make_float4(fmaxf(v[i][0], 0.f), fmaxf(v[i][1], 0.f),
                            fmaxf(v[i][2], 0.f), fmaxf(v[i][3], 0.f));
    }
}

// ---------------- BN column sums + last-block finalize ----------------
__global__ __launch_bounds__(256) void colsum_fin_kernel(const float* __restrict__ h,
                                                         const float* __restrict__ gamma,
                                                         const float* __restrict__ beta) {
    __shared__ float rs[8][33], rss[8][33];
    __shared__ int isLast;
    int f = threadIdx.x & 31, sub = threadIdx.x >> 5;
    float s = 0.f, ss = 0.f;
    for (int row = blockIdx.x * 8 + sub; row < NN; row += gridDim.x * 8) {
        float v = __ldg(h + row * 32 + f);
        s += v; ss += v * v;
    }
    rs[sub][f] = s; rss[sub][f] = ss;
    __syncthreads();
    if (threadIdx.x < 32) {
        float a = 0.f, b = 0.f;
#pragma unroll
        for (int k = 0; k < 8; k++) { a += rs[k][f]; b += rss[k][f]; }
        atomicAdd(&g_sum[f], a);
        atomicAdd(&g_ss[f], b);
    }
    __threadfence();
    if (threadIdx.x == 0)
        isLast = (atomicAdd(&g_ctr, 1) == (int)gridDim.x - 1);
    __syncthreads();
    if (isLast) {
        if (threadIdx.x < 32) {
            int j = threadIdx.x;
            float m = g_sum[j] * (1.0f / (float)NN);
            float var = g_ss[j] * (1.0f / (float)NN) - m * m;
            float sc = __ldg(gamma + j) * rsqrtf(var + 1e-5f);
            g_scale[j] = sc;
            g_shift[j] = __ldg(beta + j) - m * sc;
        }
        if (threadIdx.x == 32) g_ctr = 0;
    }
}

// ---------------- pooling ----------------
__global__ __launch_bounds__(256) void pool_kernel(const float* __restrict__ h,
                                                   const int* __restrict__ batch) {
    int node = blockIdx.x * 256 + threadIdx.x;
    if (node >= NN) return;
    int b = __ldg(batch + node);
    float* pr = g_pooled + b * 32;
    const float4* hp = (const float4*)(h + node * 32);
#pragma unroll
    for (int q = 0; q < 8; q++) {
        float4 v = hp[q];
        float4 sc = ((const float4*)g_scale)[q];
        float4 sh = ((const float4*)g_shift)[q];
        atomicAdd(pr + q * 4 + 0, v.x * sc.x + sh.x);
        atomicAdd(pr + q * 4 + 1, v.y * sc.y + sh.y);
        atomicAdd(pr + q * 4 + 2, v.z * sc.z + sh.z);
        atomicAdd(pr + q * 4 + 3, v.w * sc.w + sh.w);
    }
}

// ---------------- generic tiled GEMM (f32x2 inner) ----------------
__global__ __launch_bounds__(256) void gemm64_kernel(const float* __restrict__ A,
                                                     const float* __restrict__ B,
                                                     const float* __restrict__ bias,
                                                     float* __restrict__ C,
                                                     int M, int N, int K, int ldc, int doRelu) {
    __shared__ float As[16][68];
    __shared__ float Bs[16][68];
    int tx = threadIdx.x & 15, ty = threadIdx.x >> 4;
    int m0 = blockIdx.y * 64, n0 = blockIdx.x * 64;
    int la_m = threadIdx.x >> 2;
    int la_k = (threadIdx.x & 3) * 4;
    int lb_k = threadIdx.x >> 4;
    int lb_n = (threadIdx.x & 15) * 4;
    u64 acc2[4][2];
#pragma unroll
    for (int r = 0; r < 4; r++) { acc2[r][0] = 0ull; acc2[r][1] = 0ull; }

    for (int k0 = 0; k0 < K; k0 += 16) {
        float4 av = make_float4(0.f, 0.f, 0.f, 0.f);
        if (m0 + la_m < M) av = *(const float4*)(A + (long long)(m0 + la_m) * K + k0 + la_k);
        As[la_k + 0][la_m] = av.x; As[la_k + 1][la_m] = av.y;
        As[la_k + 2][la_m] = av.z; As[la_k + 3][la_m] = av.w;
        float4 bv = *(const float4*)(B + (long long)(k0 + lb_k) * N + n0 + lb_n);
        *(float4*)&Bs[lb_k][lb_n] = bv;
        __syncthreads();
#pragma unroll
        for (int kk = 0; kk < 16; kk++) {
            float4 a4 = *(const float4*)&As[kk][ty * 4];
            float4 b4 = *(const float4*)&Bs[kk][tx * 4];
            u64 b01 = packf2(b4.x, b4.y), b23 = packf2(b4.z, b4.w);
            u64 as;
            as = packf2(a4.x, a4.x); acc2[0][0] = fmaf2(as, b01, acc2[0][0]); acc2[0][1] = fmaf2(as, b23, acc2[0][1]);
            as = packf2(a4.y, a4.y); acc2[1][0] = fmaf2(as, b01, acc2[1][0]); acc2[1][1] = fmaf2(as, b23, acc2[1][1]);
            as = packf2(a4.z, a4.z); acc2[2][0] = fmaf2(as, b01, acc2[2][0]); acc2[2][1] = fmaf2(as, b23, acc2[2][1]);
            as = packf2(a4.w, a4.w); acc2[3][0] = fmaf2(as, b01, acc2[3][0]); acc2[3][1] = fmaf2(as, b23, acc2[3][1]);
        }
        __syncthreads();
    }
    float vv[4][4];
#pragma unroll
    for (int r = 0; r < 4; r++) {
        unpackf2(acc2[r][0], vv[r][0], vv[r][1]);
        unpackf2(acc2[r][1], vv[r][2], vv[r][3]);
    }
#pragma unroll
    for (int r = 0; r < 4; r++) {
        int row = m0 + ty * 4 + r;
        if (row >= M) continue;
#pragma unroll
        for (int c = 0; c < 4; c++) {
            int col = n0 + tx * 4 + c;
            float v = vv[r][c];
            if (bias) v += __ldg(bias + col);
            if (doRelu) v = fmaxf(v, 0.f);
            C[(long long)row * ldc + col] = v;
        }
    }
}

// ---------------- protein branch precomputes ----------------
__global__ void wtrans_kernel(const float* __restrict__ convW) {
    int i = blockIdx.x * 256 + threadIdx.x;
    if (i < SEQL * 256) {
        int c = i >> 8, ok = i & 255, o = ok >> 3, k = ok & 7;
        g_Wt[i] = convW[o * 8000 + c * 8 + k];
    }
}

// G[(o*8+k)][v*128+j] = sum_l emb[v][l+k] * Fw[(o*121+l)*128 + j]
// grid (32 o, 4 j-quarters), 256 threads (32 j x 8 k); emb staged as v-pairs (float2).
__global__ __launch_bounds__(256) void g_kernel(const float* __restrict__ emb,
                                                const float* __restrict__ Fw) {
    __shared__ float2 sEp[13 * 128];
    int o = blockIdx.x, jq = blockIdx.y;
    int t = threadIdx.x;
    for (int i = t; i < 13 * 128; i += 256) {
        int v2 = i >> 7, idx = i & 127;
        sEp[i] = make_float2(emb[(2 * v2) * 128 + idx], emb[(2 * v2 + 1) * 128 + idx]);
    }
    __syncthreads();
    int jl = t & 31, k = t >> 5;
    int j = jq * 32 + jl;
    u64 acc[13];
#pragma unroll
    for (int v2 = 0; v2 < 13; v2++) acc[v2] = 0ull;
    const float* fp = Fw + (long long)(o * 121) * 128 + j;
    const u64* eb = (const u64*)sEp;
#pragma unroll 2
    for (int l = 0; l < 121; l++) {
        float f = __ldg(fp + l * 128);
        u64 fs = packf2(f, f);
        const u64* ep = eb + (l + k);
#pragma unroll
        for (int v2 = 0; v2 < 13; v2++) acc[v2] = fmaf2(ep[v2 * 128], fs, acc[v2]);
    }
    float* gp = g_G + (long long)(o * 8 + k) * (NVOC * 128) + j;
#pragma unroll
    for (int v2 = 0; v2 < 13; v2++) {
        float lo, hi; unpackf2(acc[v2], lo, hi);
        gp[(2 * v2) * 128] = lo;
        gp[(2 * v2 + 1) * 128] = hi;
    }
}

__global__ void cb_kernel(const float* __restrict__ Fw, const float* __restrict__ convb,
                          const float* __restrict__ fcxt_b) {
    int j = threadIdx.x;
    float acc = fcxt_b[j];
    for (int o = 0; o < 32; o++) {
        float fs = 0.f;
        for (int l = 0; l < 121; l++) fs += Fw[(long long)(o * 121 + l) * 128 + j];
        acc += convb[o] * fs;
    }
    g_cb[j] = acc;
}

__global__ __launch_bounds__(256) void cbinit_kernel() {
    int i = blockIdx.x * 256 + threadIdx.x;
    if (i < BB * 128) {
        int b = i >> 7, j = i & 127;
        g_xc[b * 256 + 128 + j] = g_cb[j];
    }
}

__global__ __launch_bounds__(256) void ttrans_kernel(const int* __restrict__ target) {
    __shared__ int tile[32][33];
    int c0 = blockIdx.x * 32, b0 = blockIdx.y * 32;
    int tx = threadIdx.x & 31, ty = threadIdx.x >> 5;
#pragma unroll
    for (int r = 0; r < 4; r++) {
        int b = b0 + ty + r * 8;
        int c = c0 + tx;
        tile[ty + r * 8][tx] = (c < SEQL) ? __ldg(target + (long long)b * SEQL + c) : 0;
    }
    __syncthreads();
#pragma unroll
    for (int r = 0; r < 4; r++) {
        int c = c0 + ty + r * 8;
        int b = b0 + tx;
        if (c < SEQL) g_tT[c * BB + b] = tile[tx][ty + r * 8];
    }
}

// blocked xt: grid (8 j-chunks, 20 c-chunks), 512 threads; float4 per j-quad
__global__ __launch_bounds__(512) void xt_kernel() {
    __shared__ float4 sH4[NVOC * 4];
    __shared__ int tv[BB];
    int jc = blockIdx.x, cc = blockIdx.y;
    int t = threadIdx.x;
    int jq = t & 3, bg = t >> 2;          // 4 j-quads x 128 b-groups
    u64 acc2[8][2];
#pragma unroll
    for (int i = 0; i < 8; i++) { acc2[i][0] = 0ull; acc2[i][1] = 0ull; }
    for (int c = cc * 50; c < cc * 50 + 50; c++) {
        if (t < NVOC * 4) {
            int v = t >> 2, q = t & 3;
            sH4[t] = *(const float4*)&g_H[((long long)c * NVOC + v) * 128 + jc * 16 + q * 4];
        }
        tv[t] = g_tT[c * BB + t];
        if (t < 512) tv[t + 512] = g_tT[c * BB + t + 512];
        __syncthreads();
#pragma unroll
        for (int bi = 0; bi < 8; bi++) {
            int v = tv[bi * 128 + bg];
            const u64* hp = (const u64*)&sH4[v * 4 + jq];
            acc2[bi][0] = addf2(acc2[bi][0], hp[0]);
            acc2[bi][1] = addf2(acc2[bi][1], hp[1]);
        }
        __syncthreads();
    }
#pragma unroll
    for (int bi = 0; bi < 8; bi++) {
        int b = bi * 128 + bg;
        float v0, v1, v2, v3;
        unpackf2(acc2[bi][0], v0, v1);
        unpackf2(acc2[bi][1], v2, v3);
        float* dst = &g_xc[b * 256 + 128 + jc * 16 + jq * 4];
        atomicAdd(dst + 0, v0); atomicAdd(dst + 1, v1);
        atomicAdd(dst + 2, v2); atomicAdd(dst + 3, v3);
    }
}

__global__ void out_kernel(const float* __restrict__ W, const float* __restrict__ b,
                           float* __restrict__ out) {
    int row = blockIdx.x * 8 + (threadIdx.x >> 5);
    int lane = threadIdx.x & 31;
    if (row >= BB) return;
    float acc = 0.f;
    for (int i = lane; i < 256; i += 32) acc += g_t2[row * 256 + i] * __ldg(W + i);
#pragma unroll
    for (int off = 16; off; off >>= 1) acc += __shfl_down_sync(0xffffffffu, acc, off);
    if (lane == 0) out[row] = acc + __ldg(b);
}

// ---------------- launch ----------------
extern "C" void kernel_launch(void* const* d_in, const int* in_sizes, int n_in,
                              void* d_out, int out_size) {
    const float* x      = (const float*)d_in[0];
    const int*   ei     = (const int*)d_in[1];
    const int*   src    = ei;
    const int*   dst    = ei + NE;
    const int*   batch  = (const int*)d_in[2];
    const int*   target = (const int*)d_in[3];
    const float* W1a = (const float*)d_in[4];
    const float* b1a = (const float*)d_in[5];
    const float* W2a = (const float*)d_in[6];
    const float* b2a = (const float*)d_in[7];
    const float* g1  = (const float*)d_in[8];
    const float* be1 = (const float*)d_in[9];
    const float* Ws1 = (const float*)d_in[10];
    const float* bs1 = (const float*)d_in[11];
    const float* Ws2 = (const float*)d_in[12];
    const float* bs2 = (const float*)d_in[13];
    const float* gs  = (const float*)d_in[14];
    const float* bes = (const float*)d_in[15];
    const float* fc1xd_W = (const float*)d_in[16];
    const float* fc1xd_b = (const float*)d_in[17];
    const float* emb     = (const float*)d_in[18];
    const float* convW   = (const float*)d_in[19];
    const float* convb   = (const float*)d_in[20];
    const float* fcxt_W  = (const float*)d_in[21];
    const float* fcxt_b  = (const float*)d_in[22];
    const float* fc1_W   = (const float*)d_in[23];
    const float* fc1_b   = (const float*)d_in[24];
    const float* fc2_W   = (const float*)d_in[25];
    const float* fc2_b   = (const float*)d_in[26];
    const float* out_W   = (const float*)d_in[27];
    const float* out_b   = (const float*)d_in[28];

    float *p_h, *p_agg, *p_pooled, *p_xc, *p_t1, *p_t2, *p_Wt, *p_G, *p_H;
    cudaGetSymbolAddress((void**)&p_h, g_h);
    cudaGetSymbolAddress((void**)&p_agg, g_agg);
    cudaGetSymbolAddress((void**)&p_pooled, g_pooled);
    cudaGetSymbolAddress((void**)&p_xc, g_xc);
    cudaGetSymbolAddress((void**)&p_t1, g_t1);
    cudaGetSymbolAddress((void**)&p_t2, g_t2);
    cudaGetSymbolAddress((void**)&p_Wt, g_Wt);
    cudaGetSymbolAddress((void**)&p_G, g_G);
    cudaGetSymbolAddress((void**)&p_H, g_H);

    const int EDGE_BLOCKS = (NE + 255) / 256;       // 7813
    const int AGG_BLOCKS  = (NN * 8 + 255) / 256;   // 6250
    const int PROJ_BLOCKS = (NN + PM - 1) / PM;     // 2084
    const int NP_BLOCKS   = (NN + 127) / 128;       // 1563

    // adjacency build
    zero_kernel<<<NBLK, 256>>>();
    fill_kernel<<<EDGE_BLOCKS, 256>>>(src, dst);

    // layer-1 projection -> g_h
    proj_kernel<<<PROJ_BLOCKS, 192>>>(x, W1a, p_h);

    // layer 1
    agg_kernel<<<AGG_BLOCKS, 256>>>(p_h, p_agg, 0);
    nodepass_kernel<<<NP_BLOCKS, 256>>>(p_agg, p_h, nullptr, b1a, W2a, b2a);
    colsum_fin_kernel<<<625, 256>>>(p_h, g1, be1);

    // layers 2..5 (BN affine fused into agg)
    for (int i = 0; i < 4; i++) {
        agg_kernel<<<AGG_BLOCKS, 256>>>(p_h, p_agg, 1);
        nodepass_kernel<<<NP_BLOCKS, 256>>>(p_agg, p_h, Ws1 + i * 1024, bs1 + i * 32,
                                            Ws2 + i * 1024, bs2 + i * 32);
        colsum_fin_kernel<<<625, 256>>>(p_h, gs + i * 32, bes + i * 32);
    }

    // pooling + drug head
    pool_kernel<<<NBLK, 256>>>(p_h, batch);
    gemm64_kernel<<<dim3(128 / 64, BB / 64), 256>>>(p_pooled, fc1xd_W, fc1xd_b,
                                                    p_xc, BB, 128, 32, 256, 1);

    // protein branch
    wtrans_kernel<<<(SEQL * 256 + 255) / 256, 256>>>(convW);
    g_kernel<<<dim3(32, 4), 256>>>(emb, fcxt_W);
    cb_kernel<<<1, 128>>>(fcxt_W, convb, fcxt_b);
    cbinit_kernel<<<(BB * 128 + 255) / 256, 256>>>();
    ttrans_kernel<<<dim3((SEQL + 31) / 32, BB / 32), 256>>>(target);
    gemm64_kernel<<<dim3((NVOC * 128) / 64, (SEQL + 63) / 64), 256>>>(
        p_Wt, p_G, nullptr, p_H, SEQL, NVOC * 128, 256, NVOC * 128, 0);
    xt_kernel<<<dim3(8, 20), 512>>>();

    // joint head
    gemm64_kernel<<<dim3(1024 / 64, BB / 64), 256>>>(p_xc, fc1_W, fc1_b, p_t1, BB, 1024, 256, 1024, 1);
    gemm64_kernel<<<dim3(256 / 64, BB / 64), 256>>>(p_t1, fc2_W, fc2_b, p_t2, BB, 256, 1024, 256, 1);
    out_kernel<<<BB / 8, 256>>>(out_W, out_b, (float*)d_out);
}

// round 8
// speedup vs baseline: 1.5711x; 1.2245x over previous
#include <cuda_runtime.h>

#define NN 200000
#define NE 2000000
#define BB 1024
#define SEQL 1000
#define NVOC 26
#define PAD 48
#define NBLK ((NN + 255) / 256)   // 782

typedef unsigned long long u64;
__device__ __forceinline__ u64 packf2(float lo, float hi) {
    u64 d; asm("mov.b64 %0, {%1,%2};" : "=l"(d) : "f"(lo), "f"(hi)); return d;
}
__device__ __forceinline__ void unpackf2(u64 s, float& lo, float& hi) {
    asm("mov.b64 {%0,%1}, %2;" : "=f"(lo), "=f"(hi) : "l"(s));
}
__device__ __forceinline__ u64 fmaf2(u64 a, u64 b, u64 c) {
    u64 d; asm("fma.rn.f32x2 %0, %1, %2, %3;" : "=l"(d) : "l"(a), "l"(b), "l"(c)); return d;
}
__device__ __forceinline__ u64 addf2(u64 a, u64 b) {
    u64 d; asm("add.rn.f32x2 %0, %1, %2;" : "=l"(d) : "l"(a), "l"(b)); return d;
}

// ---------------- scratch (static __device__, no allocs) ----------------
__device__ float g_h[NN * 32];
__device__ float g_agg[NN * 32];
__device__ float g_sum[32];
__device__ float g_ss[32];
__device__ float g_scale[32];
__device__ float g_shift[32];
__device__ float g_pooled[BB * 32];
__device__ float g_xc[BB * 256];
__device__ float g_t1[BB * 1024];
__device__ float g_t2[BB * 256];
__device__ float g_Wt[SEQL * 256];          // convW transposed: [c][(o,k)]
__device__ float g_G[256 * NVOC * 128];     // [(o*8+k)][v*128+j]
__device__ float g_H[SEQL * NVOC * 128];    // [(c*26+v)*128+j]
__device__ float g_cb[128];
__device__ int   g_deg[NN];
__device__ int   g_colp[NN * PAD];
__device__ int   g_tT[SEQL * BB];
__device__ int   g_ctr;

// ================= init =================
__global__ __launch_bounds__(256) void zero_kernel() {
    int i = blockIdx.x * 256 + threadIdx.x;
    if (i < NN) g_deg[i] = 0;
    if (i < BB * 32) g_pooled[i] = 0.f;
    if (i < BB * 128) {                 // zero xt region of xc (xt accumulates)
        int b = i >> 7, j = i & 127;
        g_xc[b * 256 + 128 + j] = 0.f;
    }
    if (i == 0) g_ctr = 0;
}

__global__ __launch_bounds__(256) void fill_kernel(const int* __restrict__ src,
                                                   const int* __restrict__ dst) {
    int e = blockIdx.x * 256 + threadIdx.x;
    if (e < NE) {
        int d = __ldg(dst + e);
        int slot = atomicAdd(&g_deg[d], 1);
        if (slot < PAD) g_colp[d * PAD + slot] = __ldg(src + e);
    }
}

// ---------------- layer-1 projection: z = x @ W1a (tiled, coalesced, f32x2) --------
#define PM 96
#define PSTR 98
__global__ __launch_bounds__(192) void proj_kernel(const float* __restrict__ x,
                                                   const float* __restrict__ W,
                                                   float* __restrict__ h) {
    __shared__ float sX[78 * PSTR];   // transposed [f][m]
    __shared__ float sW[78 * 32];
    int t = threadIdx.x;
    for (int i = t; i < 78 * 32; i += 192) sW[i] = W[i];
    long long node0 = (long long)blockIdx.x * PM;
    for (int i = t; i < PM * 78; i += 192) {
        int m = i / 78, f = i - m * 78;
        float v = (node0 + m < NN) ? x[node0 * 78 + i] : 0.f;
        sX[f * PSTR + m] = v;
    }
    __syncthreads();
    int jg = t & 7, mg = t >> 3;      // 8 x 24
    int m0 = mg * 4, j0 = jg * 4;
    u64 acc[2][4];
#pragma unroll
    for (int c = 0; c < 4; c++) { acc[0][c] = 0ull; acc[1][c] = 0ull; }
#pragma unroll 2
    for (int f = 0; f < 78; f++) {
        float4 w4 = *(const float4*)&sW[f * 32 + j0];
        u64 a0 = *(const u64*)&sX[f * PSTR + m0];
        u64 a1 = *(const u64*)&sX[f * PSTR + m0 + 2];
        u64 w;
        w = packf2(w4.x, w4.x); acc[0][0] = fmaf2(a0, w, acc[0][0]); acc[1][0] = fmaf2(a1, w, acc[1][0]);
        w = packf2(w4.y, w4.y); acc[0][1] = fmaf2(a0, w, acc[0][1]); acc[1][1] = fmaf2(a1, w, acc[1][1]);
        w = packf2(w4.z, w4.z); acc[0][2] = fmaf2(a0, w, acc[0][2]); acc[1][2] = fmaf2(a1, w, acc[1][2]);
        w = packf2(w4.w, w4.w); acc[0][3] = fmaf2(a0, w, acc[0][3]); acc[1][3] = fmaf2(a1, w, acc[1][3]);
    }
    float v[4][4];
#pragma unroll
    for (int c = 0; c < 4; c++) {
        unpackf2(acc[0][c], v[0][c], v[1][c]);
        unpackf2(acc[1][c], v[2][c], v[3][c]);
    }
#pragma unroll
    for (int i = 0; i < 4; i++) {
        if (node0 + m0 + i < NN)
            *(float4*)&h[(node0 + m0 + i) * 32 + j0] =
                make_float4(v[i][0], v[i][1], v[i][2], v[i][3]);
    }
}

// ---------------- gather aggregation (+ fused BN affine) ----------------
// Block 0 zeroes the BN stat accumulators for the nodepass that follows.
__global__ __launch_bounds__(256) void agg_kernel(const float* __restrict__ h,
                                                  float* __restrict__ agg, int useNorm) {
    if (blockIdx.x == 0 && threadIdx.x < 64) {
        if (threadIdx.x < 32) g_sum[threadIdx.x] = 0.f;
        else g_ss[threadIdx.x - 32] = 0.f;
    }
    int gid = blockIdx.x * 256 + threadIdx.x;
    int node = gid >> 3, q = gid & 7;
    if (node >= NN) return;
    int deg = __ldg(&g_deg[node]);
    if (deg > PAD) deg = PAD;
    const int* cp = g_colp + node * PAD;
    float4 acc = __ldg((const float4*)(h + node * 32) + q);
    int s = 0;
    for (; s + 3 < deg; s += 4) {
        int n1 = __ldg(cp + s), n2 = __ldg(cp + s + 1);
        int n3 = __ldg(cp + s + 2), n4 = __ldg(cp + s + 3);
        float4 v1 = __ldg((const float4*)(h + n1 * 32) + q);
        float4 v2 = __ldg((const float4*)(h + n2 * 32) + q);
        float4 v3 = __ldg((const float4*)(h + n3 * 32) + q);
        float4 v4 = __ldg((const float4*)(h + n4 * 32) + q);
        acc.x += (v1.x + v2.x) + (v3.x + v4.x);
        acc.y += (v1.y + v2.y) + (v3.y + v4.y);
        acc.z += (v1.z + v2.z) + (v3.z + v4.z);
        acc.w += (v1.w + v2.w) + (v3.w + v4.w);
    }
    for (; s < deg; s++) {
        int n1 = __ldg(cp + s);
        float4 v1 = __ldg((const float4*)(h + n1 * 32) + q);
        acc.x += v1.x; acc.y += v1.y; acc.z += v1.z; acc.w += v1.w;
    }
    if (useNorm) {
        float4 sc = ((const float4*)g_scale)[q];
        float4 sh = ((const float4*)g_shift)[q];
        float cnt = (float)(deg + 1);
        acc.x = sc.x * acc.x + cnt * sh.x;
        acc.y = sc.y * acc.y + cnt * sh.y;
        acc.z = sc.z * acc.z + cnt * sh.z;
        acc.w = sc.w * acc.w + cnt * sh.w;
    }
    ((float4*)(agg + node * 32))[q] = acc;
}

// ---------------- per-node GIN MLP + relu + fused BN stats & finalize --------------
// 256 threads, 128 nodes/block. W1==nullptr -> identity (layer 1 folded in proj).
// Computes column sums/sumsq of the relu'd output in-register, block-reduces via
// smem, atomically accumulates, and the LAST block finalizes g_scale/g_shift.
__global__ __launch_bounds__(256) void nodepass_kernel(const float* __restrict__ agg,
                                                       float* __restrict__ hout,
                                                       const float* __restrict__ W1,
                                                       const float* __restrict__ b1,
                                                       const float* __restrict__ W2,
                                                       const float* __restrict__ b2,
                                                       const float* __restrict__ gamma,
                                                       const float* __restrict__ beta) {
    __shared__ float sT[32 * 130];    // transposed activations [f][m] (reused for stats)
    __shared__ float sW1[1024], sW2[1024], sb1[32], sb2[32];
    __shared__ int isLast;
    int t = threadIdx.x;
    if (W1) { for (int i = t; i < 1024; i += 256) sW1[i] = W1[i]; }
    else    { for (int i = t; i < 1024; i += 256) sW1[i] = ((i >> 5) == (i & 31)) ? 1.f : 0.f; }
    for (int i = t; i < 1024; i += 256) sW2[i] = W2[i];
    if (t < 32) { sb1[t] = b1[t]; sb2[t] = b2[t]; }
    long long node0 = (long long)blockIdx.x * 128;
#pragma unroll
    for (int r = 0; r < 4; r++) {
        int fidx = r * 1024 + t * 4;
        int m = fidx >> 5, f = fidx & 31;
        float4 v = make_float4(0.f, 0.f, 0.f, 0.f);
        if (node0 + m < NN) v = *(const float4*)(agg + (node0 + m) * 32 + f);
        sT[f * 130 + m] = v.x; sT[(f + 1) * 130 + m] = v.y;
        sT[(f + 2) * 130 + m] = v.z; sT[(f + 3) * 130 + m] = v.w;
    }
    __syncthreads();
    int jg = t & 7, mg = t >> 3;
    int m0 = mg * 4, j0 = jg * 4;
    u64 acc[2][4];
#pragma unroll
    for (int c = 0; c < 4; c++) { float bb = sb1[j0 + c]; acc[0][c] = packf2(bb, bb); acc[1][c] = acc[0][c]; }
#pragma unroll
    for (int f = 0; f < 32; f++) {
        float4 w4 = *(const float4*)&sW1[f * 32 + j0];
        u64 a0 = *(const u64*)&sT[f * 130 + m0];
        u64 a1 = *(const u64*)&sT[f * 130 + m0 + 2];
        u64 w;
        w = packf2(w4.x, w4.x); acc[0][0] = fmaf2(a0, w, acc[0][0]); acc[1][0] = fmaf2(a1, w, acc[1][0]);
        w = packf2(w4.y, w4.y); acc[0][1] = fmaf2(a0, w, acc[0][1]); acc[1][1] = fmaf2(a1, w, acc[1][1]);
        w = packf2(w4.z, w4.z); acc[0][2] = fmaf2(a0, w, acc[0][2]); acc[1][2] = fmaf2(a1, w, acc[1][2]);
        w = packf2(w4.w, w4.w); acc[0][3] = fmaf2(a0, w, acc[0][3]); acc[1][3] = fmaf2(a1, w, acc[1][3]);
    }
    __syncthreads();
#pragma unroll
    for (int c = 0; c < 4; c++) {
        float x0, x1, x2, x3;
        unpackf2(acc[0][c], x0, x1); unpackf2(acc[1][c], x2, x3);
        x0 = fmaxf(x0, 0.f); x1 = fmaxf(x1, 0.f); x2 = fmaxf(x2, 0.f); x3 = fmaxf(x3, 0.f);
        *(u64*)&sT[(j0 + c) * 130 + m0]     = packf2(x0, x1);
        *(u64*)&sT[(j0 + c) * 130 + m0 + 2] = packf2(x2, x3);
    }
    __syncthreads();
#pragma unroll
    for (int c = 0; c < 4; c++) { float bb = sb2[j0 + c]; acc[0][c] = packf2(bb, bb); acc[1][c] = acc[0][c]; }
#pragma unroll
    for (int f = 0; f < 32; f++) {
        float4 w4 = *(const float4*)&sW2[f * 32 + j0];
        u64 a0 = *(const u64*)&sT[f * 130 + m0];
        u64 a1 = *(const u64*)&sT[f * 130 + m0 + 2];
        u64 w;
        w = packf2(w4.x, w4.x); acc[0][0] = fmaf2(a0, w, acc[0][0]); acc[1][0] = fmaf2(a1, w, acc[1][0]);
        w = packf2(w4.y, w4.y); acc[0][1] = fmaf2(a0, w, acc[0][1]); acc[1][1] = fmaf2(a1, w, acc[1][1]);
        w = packf2(w4.z, w4.z); acc[0][2] = fmaf2(a0, w, acc[0][2]); acc[1][2] = fmaf2(a1, w, acc[1][2]);
        w = packf2(w4.w, w4.w); acc[0][3] = fmaf2(a0, w, acc[0][3]); acc[1][3] = fmaf2(a1, w, acc[1][3]);
    }
    float v[4][4];
#pragma unroll
    for (int c = 0; c < 4; c++) {
        unpackf2(acc[0][c], v[0][c], v[1][c]);
        unpackf2(acc[1][c], v[2][c], v[3][c]);
    }
    // relu + store + per-thread column partial sums
    float ls[4] = {0.f, 0.f, 0.f, 0.f}, lq[4] = {0.f, 0.f, 0.f, 0.f};
#pragma unroll
    for (int i = 0; i < 4; i++) {
        bool ok = (node0 + m0 + i < NN);
        float r0 = fmaxf(v[i][0], 0.f), r1 = fmaxf(v[i][1], 0.f);
        float r2 = fmaxf(v[i][2], 0.f), r3 = fmaxf(v[i][3], 0.f);
        if (ok) {
            *(float4*)&hout[(node0 + m0 + i) * 32 + j0] = make_float4(r0, r1, r2, r3);
            ls[0] += r0; ls[1] += r1; ls[2] += r2; ls[3] += r3;
            lq[0] += r0 * r0; lq[1] += r1 * r1; lq[2] += r2 * r2; lq[3] += r3 * r3;
        }
    }
    // block reduce: sT reused as [32 mg][33] x2
    __syncthreads();
    float* sS = sT;               // 32*33
    float* sQ = sT + 32 * 33;     // 32*33
#pragma unroll
    for (int c = 0; c < 4; c++) {
        sS[mg * 33 + j0 + c] = ls[c];
        sQ[mg * 33 + j0 + c] = lq[c];
    }
    __syncthreads();
    if (t < 32) {
        float a = 0.f, b = 0.f;
#pragma unroll
        for (int r = 0; r < 32; r++) { a += sS[r * 33 + t]; b += sQ[r * 33 + t]; }
        atomicAdd(&g_sum[t], a);
        atomicAdd(&g_ss[t], b);
    }
    __threadfence();
    if (t == 0) isLast = (atomicAdd(&g_ctr, 1) == (int)gridDim.x - 1);
    __syncthreads();
    if (isLast) {
        if (t < 32) {
            float m = g_sum[t] * (1.0f / (float)NN);
            float var = g_ss[t] * (1.0f / (float)NN) - m * m;
            float sc = __ldg(gamma + t) * rsqrtf(var + 1e-5f);
            g_scale[t] = sc;
            g_shift[t] = __ldg(beta + t) - m * sc;
        }
        if (t == 32) g_ctr = 0;
    }
}

// ---------------- pooling: pooled[batch[i]] += normalize(h[i]) ----------------
__global__ __launch_bounds__(256) void pool_kernel(const float* __restrict__ h,
                                                   const int* __restrict__ batch) {
    int node = blockIdx.x * 256 + threadIdx.x;
    if (node >= NN) return;
    int b = __ldg(batch + node);
    float* pr = g_pooled + b * 32;
    const float4* hp = (const float4*)(h + node * 32);
#pragma unroll
    for (int q = 0; q < 8; q++) {
        float4 v = hp[q];
        float4 sc = ((const float4*)g_scale)[q];
        float4 sh = ((const float4*)g_shift)[q];
        atomicAdd(pr + q * 4 + 0, v.x * sc.x + sh.x);
        atomicAdd(pr + q * 4 + 1, v.y * sc.y + sh.y);
        atomicAdd(pr + q * 4 + 2, v.z * sc.z + sh.z);
        atomicAdd(pr + q * 4 + 3, v.w * sc.w + sh.w);
    }
}

// ---------------- generic tiled GEMM (f32x2 inner) ----------------
__global__ __launch_bounds__(256) void gemm64_kernel(const float* __restrict__ A,
                                                     const float* __restrict__ B,
                                                     const float* __restrict__ bias,
                                                     float* __restrict__ C,
                                                     int M, int N, int K, int ldc, int doRelu) {
    __shared__ float As[16][68];
    __shared__ float Bs[16][68];
    int tx = threadIdx.x & 15, ty = threadIdx.x >> 4;
    int m0 = blockIdx.y * 64, n0 = blockIdx.x * 64;
    int la_m = threadIdx.x >> 2;
    int la_k = (threadIdx.x & 3) * 4;
    int lb_k = threadIdx.x >> 4;
    int lb_n = (threadIdx.x & 15) * 4;
    u64 acc2[4][2];
#pragma unroll
    for (int r = 0; r < 4; r++) { acc2[r][0] = 0ull; acc2[r][1] = 0ull; }

    for (int k0 = 0; k0 < K; k0 += 16) {
        float4 av = make_float4(0.f, 0.f, 0.f, 0.f);
        if (m0 + la_m < M) av = *(const float4*)(A + (long long)(m0 + la_m) * K + k0 + la_k);
        As[la_k + 0][la_m] = av.x; As[la_k + 1][la_m] = av.y;
        As[la_k + 2][la_m] = av.z; As[la_k + 3][la_m] = av.w;
        float4 bv = *(const float4*)(B + (long long)(k0 + lb_k) * N + n0 + lb_n);
        *(float4*)&Bs[lb_k][lb_n] = bv;
        __syncthreads();
#pragma unroll
        for (int kk = 0; kk < 16; kk++) {
            float4 a4 = *(const float4*)&As[kk][ty * 4];
            float4 b4 = *(const float4*)&Bs[kk][tx * 4];
            u64 b01 = packf2(b4.x, b4.y), b23 = packf2(b4.z, b4.w);
            u64 as;
            as = packf2(a4.x, a4.x); acc2[0][0] = fmaf2(as, b01, acc2[0][0]); acc2[0][1] = fmaf2(as, b23, acc2[0][1]);
            as = packf2(a4.y, a4.y); acc2[1][0] = fmaf2(as, b01, acc2[1][0]); acc2[1][1] = fmaf2(as, b23, acc2[1][1]);
            as = packf2(a4.z, a4.z); acc2[2][0] = fmaf2(as, b01, acc2[2][0]); acc2[2][1] = fmaf2(as, b23, acc2[2][1]);
            as = packf2(a4.w, a4.w); acc2[3][0] = fmaf2(as, b01, acc2[3][0]); acc2[3][1] = fmaf2(as, b23, acc2[3][1]);
        }
        __syncthreads();
    }
    float vv[4][4];
#pragma unroll
    for (int r = 0; r < 4; r++) {
        unpackf2(acc2[r][0], vv[r][0], vv[r][1]);
        unpackf2(acc2[r][1], vv[r][2], vv[r][3]);
    }
#pragma unroll
    for (int r = 0; r < 4; r++) {
        int row = m0 + ty * 4 + r;
        if (row >= M) continue;
#pragma unroll
        for (int c = 0; c < 4; c++) {
            int col = n0 + tx * 4 + c;
            float v = vv[r][c];
            if (bias) v += __ldg(bias + col);
            if (doRelu) v = fmaxf(v, 0.f);
            C[(long long)row * ldc + col] = v;
        }
    }
}

// ---------------- protein branch precomputes ----------------
__global__ void wtrans_kernel(const float* __restrict__ convW) {
    int i = blockIdx.x * 256 + threadIdx.x;
    if (i < SEQL * 256) {
        int c = i >> 8, ok = i & 255, o = ok >> 3, k = ok & 7;
        g_Wt[i] = convW[o * 8000 + c * 8 + k];
    }
}

// G[(o*8+k)][v*128+j] = sum_l emb[v][l+k] * Fw[(o*121+l)*128 + j]
__global__ __launch_bounds__(256) void g_kernel(const float* __restrict__ emb,
                                                const float* __restrict__ Fw) {
    __shared__ float2 sEp[13 * 128];
    int o = blockIdx.x, jq = blockIdx.y;
    int t = threadIdx.x;
    for (int i = t; i < 13 * 128; i += 256) {
        int v2 = i >> 7, idx = i & 127;
        sEp[i] = make_float2(emb[(2 * v2) * 128 + idx], emb[(2 * v2 + 1) * 128 + idx]);
    }
    __syncthreads();
    int jl = t & 31, k = t >> 5;
    int j = jq * 32 + jl;
    u64 acc[13];
#pragma unroll
    for (int v2 = 0; v2 < 13; v2++) acc[v2] = 0ull;
    const float* fp = Fw + (long long)(o * 121) * 128 + j;
    const u64* eb = (const u64*)sEp;
#pragma unroll 2
    for (int l = 0; l < 121; l++) {
        float f = __ldg(fp + l * 128);
        u64 fs = packf2(f, f);
        const u64* ep = eb + (l + k);
#pragma unroll
        for (int v2 = 0; v2 < 13; v2++) acc[v2] = fmaf2(ep[v2 * 128], fs, acc[v2]);
    }
    float* gp = g_G + (long long)(o * 8 + k) * (NVOC * 128) + j;
#pragma unroll
    for (int v2 = 0; v2 < 13; v2++) {
        float lo, hi; unpackf2(acc[v2], lo, hi);
        gp[(2 * v2) * 128] = lo;
        gp[(2 * v2 + 1) * 128] = hi;
    }
}

// cb[j] = fcxt_b[j] + sum_o convb[o] * sum_l Fw[(o*121+l)*128+j]   (grid 128, block 32)
__global__ void cb_kernel(const float* __restrict__ Fw, const float* __restrict__ convb,
                          const float* __restrict__ fcxt_b) {
    int j = blockIdx.x, o = threadIdx.x;
    float fs = 0.f;
    for (int l = 0; l < 121; l++) fs += __ldg(&Fw[(long long)(o * 121 + l) * 128 + j]);
    float a = __ldg(convb + o) * fs;
#pragma unroll
    for (int off = 16; off; off >>= 1) a += __shfl_down_sync(0xffffffffu, a, off);
    if (o == 0) g_cb[j] = __ldg(fcxt_b + j) + a;
}

__global__ __launch_bounds__(256) void ttrans_kernel(const int* __restrict__ target) {
    __shared__ int tile[32][33];
    int c0 = blockIdx.x * 32, b0 = blockIdx.y * 32;
    int tx = threadIdx.x & 31, ty = threadIdx.x >> 5;
#pragma unroll
    for (int r = 0; r < 4; r++) {
        int b = b0 + ty + r * 8;
        int c = c0 + tx;
        tile[ty + r * 8][tx] = (c < SEQL) ? __ldg(target + (long long)b * SEQL + c) : 0;
    }
    __syncthreads();
#pragma unroll
    for (int r = 0; r < 4; r++) {
        int c = c0 + ty + r * 8;
        int b = b0 + tx;
        if (c < SEQL) g_tT[c * BB + b] = tile[tx][ty + r * 8];
    }
}

// blocked xt: grid (8 j-chunks, 20 c-chunks), 512 threads; cc==0 blocks add cb
__global__ __launch_bounds__(512) void xt_kernel() {
    __shared__ float4 sH4[NVOC * 4];
    __shared__ int tv[BB];
    int jc = blockIdx.x, cc = blockIdx.y;
    int t = threadIdx.x;
    int jq = t & 3, bg = t >> 2;          // 4 j-quads x 128 b-groups
    u64 acc2[8][2];
#pragma unroll
    for (int i = 0; i < 8; i++) { acc2[i][0] = 0ull; acc2[i][1] = 0ull; }
    for (int c = cc * 50; c < cc * 50 + 50; c++) {
        if (t < NVOC * 4) {
            int v = t >> 2, q = t & 3;
            sH4[t] = *(const float4*)&g_H[((long long)c * NVOC + v) * 128 + jc * 16 + q * 4];
        }
        tv[t] = g_tT[c * BB + t];
        if (t < 512) tv[t + 512] = g_tT[c * BB + t + 512];
        __syncthreads();
#pragma unroll
        for (int bi = 0; bi < 8; bi++) {
            int v = tv[bi * 128 + bg];
            const u64* hp = (const u64*)&sH4[v * 4 + jq];
            acc2[bi][0] = addf2(acc2[bi][0], hp[0]);
            acc2[bi][1] = addf2(acc2[bi][1], hp[1]);
        }
        __syncthreads();
    }
    if (cc == 0) {
        float4 cb4 = *(const float4*)&g_cb[jc * 16 + jq * 4];
        u64 c01 = packf2(cb4.x, cb4.y), c23 = packf2(cb4.z, cb4.w);
#pragma unroll
        for (int bi = 0; bi < 8; bi++) {
            acc2[bi][0] = addf2(acc2[bi][0], c01);
            acc2[bi][1] = addf2(acc2[bi][1], c23);
        }
    }
#pragma unroll
    for (int bi = 0; bi < 8; bi++) {
        int b = bi * 128 + bg;
        float v0, v1, v2, v3;
        unpackf2(acc2[bi][0], v0, v1);
        unpackf2(acc2[bi][1], v2, v3);
        float* dst = &g_xc[b * 256 + 128 + jc * 16 + jq * 4];
        atomicAdd(dst + 0, v0); atomicAdd(dst + 1, v1);
        atomicAdd(dst + 2, v2); atomicAdd(dst + 3, v3);
    }
}

__global__ void out_kernel(const float* __restrict__ W, const float* __restrict__ b,
                           float* __restrict__ out) {
    int row = blockIdx.x * 8 + (threadIdx.x >> 5);
    int lane = threadIdx.x & 31;
    if (row >= BB) return;
    float acc = 0.f;
    for (int i = lane; i < 256; i += 32) acc += g_t2[row * 256 + i] * __ldg(W + i);
#pragma unroll
    for (int off = 16; off; off >>= 1) acc += __shfl_down_sync(0xffffffffu, acc, off);
    if (lane == 0) out[row] = acc + __ldg(b);
}

// ---------------- launch ----------------
extern "C" void kernel_launch(void* const* d_in, const int* in_sizes, int n_in,
                              void* d_out, int out_size) {
    const float* x      = (const float*)d_in[0];
    const int*   ei     = (const int*)d_in[1];
    const int*   src    = ei;
    const int*   dst    = ei + NE;
    const int*   batch  = (const int*)d_in[2];
    const int*   target = (const int*)d_in[3];
    const float* W1a = (const float*)d_in[4];
    const float* b1a = (const float*)d_in[5];
    const float* W2a = (const float*)d_in[6];
    const float* b2a = (const float*)d_in[7];
    const float* g1  = (const float*)d_in[8];
    const float* be1 = (const float*)d_in[9];
    const float* Ws1 = (const float*)d_in[10];
    const float* bs1 = (const float*)d_in[11];
    const float* Ws2 = (const float*)d_in[12];
    const float* bs2 = (const float*)d_in[13];
    const float* gs  = (const float*)d_in[14];
    const float* bes = (const float*)d_in[15];
    const float* fc1xd_W = (const float*)d_in[16];
    const float* fc1xd_b = (const float*)d_in[17];
    const float* emb     = (const float*)d_in[18];
    const float* convW   = (const float*)d_in[19];
    const float* convb   = (const float*)d_in[20];
    const float* fcxt_W  = (const float*)d_in[21];
    const float* fcxt_b  = (const float*)d_in[22];
    const float* fc1_W   = (const float*)d_in[23];
    const float* fc1_b   = (const float*)d_in[24];
    const float* fc2_W   = (const float*)d_in[25];
    const float* fc2_b   = (const float*)d_in[26];
    const float* out_W   = (const float*)d_in[27];
    const float* out_b   = (const float*)d_in[28];

    float *p_h, *p_agg, *p_pooled, *p_xc, *p_t1, *p_t2, *p_Wt, *p_G, *p_H;
    cudaGetSymbolAddress((void**)&p_h, g_h);
    cudaGetSymbolAddress((void**)&p_agg, g_agg);
    cudaGetSymbolAddress((void**)&p_pooled, g_pooled);
    cudaGetSymbolAddress((void**)&p_xc, g_xc);
    cudaGetSymbolAddress((void**)&p_t1, g_t1);
    cudaGetSymbolAddress((void**)&p_t2, g_t2);
    cudaGetSymbolAddress((void**)&p_Wt, g_Wt);
    cudaGetSymbolAddress((void**)&p_G, g_G);
    cudaGetSymbolAddress((void**)&p_H, g_H);

    const int EDGE_BLOCKS = (NE + 255) / 256;       // 7813
    const int AGG_BLOCKS  = (NN * 8 + 255) / 256;   // 6250
    const int PROJ_BLOCKS = (NN + PM - 1) / PM;     // 2084
    const int NP_BLOCKS   = (NN + 127) / 128;       // 1563

    // adjacency build (+ zero pooled / xc-xt region / ctr)
    zero_kernel<<<NBLK, 256>>>();
    fill_kernel<<<EDGE_BLOCKS, 256>>>(src, dst);

    // layer-1 projection -> g_h
    proj_kernel<<<PROJ_BLOCKS, 192>>>(x, W1a, p_h);

    // layer 1 (stats+finalize fused into nodepass)
    agg_kernel<<<AGG_BLOCKS, 256>>>(p_h, p_agg, 0);
    nodepass_kernel<<<NP_BLOCKS, 256>>>(p_agg, p_h, nullptr, b1a, W2a, b2a, g1, be1);

    // layers 2..5
    for (int i = 0; i < 4; i++) {
        agg_kernel<<<AGG_BLOCKS, 256>>>(p_h, p_agg, 1);
        nodepass_kernel<<<NP_BLOCKS, 256>>>(p_agg, p_h, Ws1 + i * 1024, bs1 + i * 32,
                                            Ws2 + i * 1024, bs2 + i * 32,
                                            gs + i * 32, bes + i * 32);
    }

    // pooling + drug head
    pool_kernel<<<NBLK, 256>>>(p_h, batch);
    gemm64_kernel<<<dim3(128 / 64, BB / 64), 256>>>(p_pooled, fc1xd_W, fc1xd_b,
                                                    p_xc, BB, 128, 32, 256, 1);

    // protein branch
    wtrans_kernel<<<(SEQL * 256 + 255) / 256, 256>>>(convW);
    g_kernel<<<dim3(32, 4), 256>>>(emb, fcxt_W);
    cb_kernel<<<128, 32>>>(fcxt_W, convb, fcxt_b);
    ttrans_kernel<<<dim3((SEQL + 31) / 32, BB / 32), 256>>>(target);
    gemm64_kernel<<<dim3((NVOC * 128) / 64, (SEQL + 63) / 64), 256>>>(
        p_Wt, p_G, nullptr, p_H, SEQL, NVOC * 128, 256, NVOC * 128, 0);
    xt_kernel<<<dim3(8, 20), 512>>>();

    // joint head
    gemm64_kernel<<<dim3(1024 / 64, BB / 64), 256>>>(p_xc, fc1_W, fc1_b, p_t1, BB, 1024, 256, 1024, 1);
    gemm64_kernel<<<dim3(256 / 64, BB / 64), 256>>>(p_t1, fc2_W, fc2_b, p_t2, BB, 256, 1024, 256, 1);
    out_kernel<<<BB / 8, 256>>>(out_W, out_b, (float*)d_out);
}

// round 9
// speedup vs baseline: 1.6311x; 1.0382x over previous
#include <cuda_runtime.h>

#define NN 200000
#define NE 2000000
#define BB 1024
#define SEQL 1000
#define NVOC 26
#define PAD 48
#define NBLK ((NN + 255) / 256)   // 782

typedef unsigned long long u64;
__device__ __forceinline__ u64 packf2(float lo, float hi) {
    u64 d; asm("mov.b64 %0, {%1,%2};" : "=l"(d) : "f"(lo), "f"(hi)); return d;
}
__device__ __forceinline__ void unpackf2(u64 s, float& lo, float& hi) {
    asm("mov.b64 {%0,%1}, %2;" : "=f"(lo), "=f"(hi) : "l"(s));
}
__device__ __forceinline__ u64 fmaf2(u64 a, u64 b, u64 c) {
    u64 d; asm("fma.rn.f32x2 %0, %1, %2, %3;" : "=l"(d) : "l"(a), "l"(b), "l"(c)); return d;
}
__device__ __forceinline__ u64 addf2(u64 a, u64 b) {
    u64 d; asm("add.rn.f32x2 %0, %1, %2;" : "=l"(d) : "l"(a), "l"(b)); return d;
}

// ---------------- scratch (static __device__, no allocs) ----------------
__device__ float g_h[NN * 32];
__device__ float g_agg[NN * 32];
__device__ float g_sum[32];
__device__ float g_ss[32];
__device__ float g_scale[32];
__device__ float g_shift[32];
__device__ float g_pooled[BB * 32];
__device__ float g_xc[BB * 256];
__device__ float g_t1[BB * 1024];
__device__ float g_t2[BB * 256];
__device__ float g_Wt[SEQL * 256];          // convW transposed: [c][(o,k)]
__device__ float g_G[256 * NVOC * 128];     // [(o*8+k)][v*128+j]
__device__ float g_H[SEQL * NVOC * 128];    // [(c*26+v)*128+j]
__device__ float g_cb[128];
__device__ int   g_deg[NN];
__device__ int   g_colp[NN * PAD];
__device__ int   g_tT[SEQL * BB];
__device__ int   g_ctr;

// ================= init =================
__global__ __launch_bounds__(256) void zero_kernel() {
    int i = blockIdx.x * 256 + threadIdx.x;
    if (i < NN) g_deg[i] = 0;
    if (i < BB * 32) g_pooled[i] = 0.f;
    if (i < BB * 128) {                 // zero xt region of xc (xt accumulates)
        int b = i >> 7, j = i & 127;
        g_xc[b * 256 + 128 + j] = 0.f;
    }
    if (i == 0) g_ctr = 0;
}

__global__ __launch_bounds__(256) void fill_kernel(const int* __restrict__ src,
                                                   const int* __restrict__ dst) {
    int e = blockIdx.x * 256 + threadIdx.x;
    if (e < NE) {
        int d = __ldg(dst + e);
        int slot = atomicAdd(&g_deg[d], 1);
        if (slot < PAD) g_colp[d * PAD + slot] = __ldg(src + e);
    }
}

// ---------------- layer-1 projection: z = x @ W1a (tiled, coalesced, f32x2) --------
#define PM 96
#define PSTR 98
__global__ __launch_bounds__(192) void proj_kernel(const float* __restrict__ x,
                                                   const float* __restrict__ W,
                                                   float* __restrict__ h) {
    __shared__ float sX[78 * PSTR];   // transposed [f][m]
    __shared__ float sW[78 * 32];
    int t = threadIdx.x;
    for (int i = t; i < 78 * 32; i += 192) sW[i] = W[i];
    long long node0 = (long long)blockIdx.x * PM;
    for (int i = t; i < PM * 78; i += 192) {
        int m = i / 78, f = i - m * 78;
        float v = (node0 + m < NN) ? x[node0 * 78 + i] : 0.f;
        sX[f * PSTR + m] = v;
    }
    __syncthreads();
    int jg = t & 7, mg = t >> 3;      // 8 x 24
    int m0 = mg * 4, j0 = jg * 4;
    u64 acc[2][4];
#pragma unroll
    for (int c = 0; c < 4; c++) { acc[0][c] = 0ull; acc[1][c] = 0ull; }
#pragma unroll 2
    for (int f = 0; f < 78; f++) {
        float4 w4 = *(const float4*)&sW[f * 32 + j0];
        u64 a0 = *(const u64*)&sX[f * PSTR + m0];
        u64 a1 = *(const u64*)&sX[f * PSTR + m0 + 2];
        u64 w;
        w = packf2(w4.x, w4.x); acc[0][0] = fmaf2(a0, w, acc[0][0]); acc[1][0] = fmaf2(a1, w, acc[1][0]);
        w = packf2(w4.y, w4.y); acc[0][1] = fmaf2(a0, w, acc[0][1]); acc[1][1] = fmaf2(a1, w, acc[1][1]);
        w = packf2(w4.z, w4.z); acc[0][2] = fmaf2(a0, w, acc[0][2]); acc[1][2] = fmaf2(a1, w, acc[1][2]);
        w = packf2(w4.w, w4.w); acc[0][3] = fmaf2(a0, w, acc[0][3]); acc[1][3] = fmaf2(a1, w, acc[1][3]);
    }
    float v[4][4];
#pragma unroll
    for (int c = 0; c < 4; c++) {
        unpackf2(acc[0][c], v[0][c], v[1][c]);
        unpackf2(acc[1][c], v[2][c], v[3][c]);
    }
#pragma unroll
    for (int i = 0; i < 4; i++) {
        if (node0 + m0 + i < NN)
            *(float4*)&h[(node0 + m0 + i) * 32 + j0] =
                make_float4(v[i][0], v[i][1], v[i][2], v[i][3]);
    }
}

// ---------------- gather aggregation (+ fused BN affine) ----------------
__global__ __launch_bounds__(256) void agg_kernel(const float* __restrict__ h,
                                                  float* __restrict__ agg, int useNorm) {
    if (blockIdx.x == 0 && threadIdx.x < 64) {
        if (threadIdx.x < 32) g_sum[threadIdx.x] = 0.f;
        else g_ss[threadIdx.x - 32] = 0.f;
    }
    int gid = blockIdx.x * 256 + threadIdx.x;
    int node = gid >> 3, q = gid & 7;
    if (node >= NN) return;
    int deg = __ldg(&g_deg[node]);
    if (deg > PAD) deg = PAD;
    const int* cp = g_colp + node * PAD;
    float4 acc = __ldg((const float4*)(h + node * 32) + q);
    int s = 0;
    for (; s + 3 < deg; s += 4) {
        int n1 = __ldg(cp + s), n2 = __ldg(cp + s + 1);
        int n3 = __ldg(cp + s + 2), n4 = __ldg(cp + s + 3);
        float4 v1 = __ldg((const float4*)(h + n1 * 32) + q);
        float4 v2 = __ldg((const float4*)(h + n2 * 32) + q);
        float4 v3 = __ldg((const float4*)(h + n3 * 32) + q);
        float4 v4 = __ldg((const float4*)(h + n4 * 32) + q);
        acc.x += (v1.x + v2.x) + (v3.x + v4.x);
        acc.y += (v1.y + v2.y) + (v3.y + v4.y);
        acc.z += (v1.z + v2.z) + (v3.z + v4.z);
        acc.w += (v1.w + v2.w) + (v3.w + v4.w);
    }
    for (; s < deg; s++) {
        int n1 = __ldg(cp + s);
        float4 v1 = __ldg((const float4*)(h + n1 * 32) + q);
        acc.x += v1.x; acc.y += v1.y; acc.z += v1.z; acc.w += v1.w;
    }
    if (useNorm) {
        float4 sc = ((const float4*)g_scale)[q];
        float4 sh = ((const float4*)g_shift)[q];
        float cnt = (float)(deg + 1);
        acc.x = sc.x * acc.x + cnt * sh.x;
        acc.y = sc.y * acc.y + cnt * sh.y;
        acc.z = sc.z * acc.z + cnt * sh.z;
        acc.w = sc.w * acc.w + cnt * sh.w;
    }
    ((float4*)(agg + node * 32))[q] = acc;
}

// ---------------- per-node GIN MLP + relu + fused BN stats & finalize --------------
__global__ __launch_bounds__(256) void nodepass_kernel(const float* __restrict__ agg,
                                                       float* __restrict__ hout,
                                                       const float* __restrict__ W1,
                                                       const float* __restrict__ b1,
                                                       const float* __restrict__ W2,
                                                       const float* __restrict__ b2,
                                                       const float* __restrict__ gamma,
                                                       const float* __restrict__ beta) {
    __shared__ float sT[32 * 130];
    __shared__ float sW1[1024], sW2[1024], sb1[32], sb2[32];
    __shared__ int isLast;
    int t = threadIdx.x;
    if (W1) { for (int i = t; i < 1024; i += 256) sW1[i] = W1[i]; }
    else    { for (int i = t; i < 1024; i += 256) sW1[i] = ((i >> 5) == (i & 31)) ? 1.f : 0.f; }
    for (int i = t; i < 1024; i += 256) sW2[i] = W2[i];
    if (t < 32) { sb1[t] = b1[t]; sb2[t] = b2[t]; }
    long long node0 = (long long)blockIdx.x * 128;
#pragma unroll
    for (int r = 0; r < 4; r++) {
        int fidx = r * 1024 + t * 4;
        int m = fidx >> 5, f = fidx & 31;
        float4 v = make_float4(0.f, 0.f, 0.f, 0.f);
        if (node0 + m < NN) v = *(const float4*)(agg + (node0 + m) * 32 + f);
        sT[f * 130 + m] = v.x; sT[(f + 1) * 130 + m] = v.y;
        sT[(f + 2) * 130 + m] = v.z; sT[(f + 3) * 130 + m] = v.w;
    }
    __syncthreads();
    int jg = t & 7, mg = t >> 3;
    int m0 = mg * 4, j0 = jg * 4;
    u64 acc[2][4];
#pragma unroll
    for (int c = 0; c < 4; c++) { float bb = sb1[j0 + c]; acc[0][c] = packf2(bb, bb); acc[1][c] = acc[0][c]; }
#pragma unroll
    for (int f = 0; f < 32; f++) {
        float4 w4 = *(const float4*)&sW1[f * 32 + j0];
        u64 a0 = *(const u64*)&sT[f * 130 + m0];
        u64 a1 = *(const u64*)&sT[f * 130 + m0 + 2];
        u64 w;
        w = packf2(w4.x, w4.x); acc[0][0] = fmaf2(a0, w, acc[0][0]); acc[1][0] = fmaf2(a1, w, acc[1][0]);
        w = packf2(w4.y, w4.y); acc[0][1] = fmaf2(a0, w, acc[0][1]); acc[1][1] = fmaf2(a1, w, acc[1][1]);
        w = packf2(w4.z, w4.z); acc[0][2] = fmaf2(a0, w, acc[0][2]); acc[1][2] = fmaf2(a1, w, acc[1][2]);
        w = packf2(w4.w, w4.w); acc[0][3] = fmaf2(a0, w, acc[0][3]); acc[1][3] = fmaf2(a1, w, acc[1][3]);
    }
    __syncthreads();
#pragma unroll
    for (int c = 0; c < 4; c++) {
        float x0, x1, x2, x3;
        unpackf2(acc[0][c], x0, x1); unpackf2(acc[1][c], x2, x3);
        x0 = fmaxf(x0, 0.f); x1 = fmaxf(x1, 0.f); x2 = fmaxf(x2, 0.f); x3 = fmaxf(x3, 0.f);
        *(u64*)&sT[(j0 + c) * 130 + m0]     = packf2(x0, x1);
        *(u64*)&sT[(j0 + c) * 130 + m0 + 2] = packf2(x2, x3);
    }
    __syncthreads();
#pragma unroll
    for (int c = 0; c < 4; c++) { float bb = sb2[j0 + c]; acc[0][c] = packf2(bb, bb); acc[1][c] = acc[0][c]; }
#pragma unroll
    for (int f = 0; f < 32; f++) {
        float4 w4 = *(const float4*)&sW2[f * 32 + j0];
        u64 a0 = *(const u64*)&sT[f * 130 + m0];
        u64 a1 = *(const u64*)&sT[f * 130 + m0 + 2];
        u64 w;
        w = packf2(w4.x, w4.x); acc[0][0] = fmaf2(a0, w, acc[0][0]); acc[1][0] = fmaf2(a1, w, acc[1][0]);
        w = packf2(w4.y, w4.y); acc[0][1] = fmaf2(a0, w, acc[0][1]); acc[1][1] = fmaf2(a1, w, acc[1][1]);
        w = packf2(w4.z, w4.z); acc[0][2] = fmaf2(a0, w, acc[0][2]); acc[1][2] = fmaf2(a1, w, acc[1][2]);
        w = packf2(w4.w, w4.w); acc[0][3] = fmaf2(a0, w, acc[0][3]); acc[1][3] = fmaf2(a1, w, acc[1][3]);
    }
    float v[4][4];
#pragma unroll
    for (int c = 0; c < 4; c++) {
        unpackf2(acc[0][c], v[0][c], v[1][c]);
        unpackf2(acc[1][c], v[2][c], v[3][c]);
    }
    float ls[4] = {0.f, 0.f, 0.f, 0.f}, lq[4] = {0.f, 0.f, 0.f, 0.f};
#pragma unroll
    for (int i = 0; i < 4; i++) {
        bool ok = (node0 + m0 + i < NN);
        float r0 = fmaxf(v[i][0], 0.f), r1 = fmaxf(v[i][1], 0.f);
        float r2 = fmaxf(v[i][2], 0.f), r3 = fmaxf(v[i][3], 0.f);
        if (ok) {
            *(float4*)&hout[(node0 + m0 + i) * 32 + j0] = make_float4(r0, r1, r2, r3);
            ls[0] += r0; ls[1] += r1; ls[2] += r2; ls[3] += r3;
            lq[0] += r0 * r0; lq[1] += r1 * r1; lq[2] += r2 * r2; lq[3] += r3 * r3;
        }
    }
    __syncthreads();
    float* sS = sT;
    float* sQ = sT + 32 * 33;
#pragma unroll
    for (int c = 0; c < 4; c++) {
        sS[mg * 33 + j0 + c] = ls[c];
        sQ[mg * 33 + j0 + c] = lq[c];
    }
    __syncthreads();
    if (t < 32) {
        float a = 0.f, b = 0.f;
#pragma unroll
        for (int r = 0; r < 32; r++) { a += sS[r * 33 + t]; b += sQ[r * 33 + t]; }
        atomicAdd(&g_sum[t], a);
        atomicAdd(&g_ss[t], b);
    }
    __threadfence();
    if (t == 0) isLast = (atomicAdd(&g_ctr, 1) == (int)gridDim.x - 1);
    __syncthreads();
    if (isLast) {
        if (t < 32) {
            float m = g_sum[t] * (1.0f / (float)NN);
            float var = g_ss[t] * (1.0f / (float)NN) - m * m;
            float sc = __ldg(gamma + t) * rsqrtf(var + 1e-5f);
            g_scale[t] = sc;
            g_shift[t] = __ldg(beta + t) - m * sc;
        }
        if (t == 32) g_ctr = 0;
    }
}

// ---------------- pooling ----------------
__global__ __launch_bounds__(256) void pool_kernel(const float* __restrict__ h,
                                                   const int* __restrict__ batch) {
    int node = blockIdx.x * 256 + threadIdx.x;
    if (node >= NN) return;
    int b = __ldg(batch + node);
    float* pr = g_pooled + b * 32;
    const float4* hp = (const float4*)(h + node * 32);
#pragma unroll
    for (int q = 0; q < 8; q++) {
        float4 v = hp[q];
        float4 sc = ((const float4*)g_scale)[q];
        float4 sh = ((const float4*)g_shift)[q];
        atomicAdd(pr + q * 4 + 0, v.x * sc.x + sh.x);
        atomicAdd(pr + q * 4 + 1, v.y * sc.y + sh.y);
        atomicAdd(pr + q * 4 + 2, v.z * sc.z + sh.z);
        atomicAdd(pr + q * 4 + 3, v.w * sc.w + sh.w);
    }
}

// ---------------- generic tiled GEMM (f32x2 inner) ----------------
__global__ __launch_bounds__(256) void gemm64_kernel(const float* __restrict__ A,
                                                     const float* __restrict__ B,
                                                     const float* __restrict__ bias,
                                                     float* __restrict__ C,
                                                     int M, int N, int K, int ldc, int doRelu) {
    __shared__ float As[16][68];
    __shared__ float Bs[16][68];
    int tx = threadIdx.x & 15, ty = threadIdx.x >> 4;
    int m0 = blockIdx.y * 64, n0 = blockIdx.x * 64;
    int la_m = threadIdx.x >> 2;
    int la_k = (threadIdx.x & 3) * 4;
    int lb_k = threadIdx.x >> 4;
    int lb_n = (threadIdx.x & 15) * 4;
    u64 acc2[4][2];
#pragma unroll
    for (int r = 0; r < 4; r++) { acc2[r][0] = 0ull; acc2[r][1] = 0ull; }

    for (int k0 = 0; k0 < K; k0 += 16) {
        float4 av = make_float4(0.f, 0.f, 0.f, 0.f);
        if (m0 + la_m < M) av = *(const float4*)(A + (long long)(m0 + la_m) * K + k0 + la_k);
        As[la_k + 0][la_m] = av.x; As[la_k + 1][la_m] = av.y;
        As[la_k + 2][la_m] = av.z; As[la_k + 3][la_m] = av.w;
        float4 bv = *(const float4*)(B + (long long)(k0 + lb_k) * N + n0 + lb_n);
        *(float4*)&Bs[lb_k][lb_n] = bv;
        __syncthreads();
#pragma unroll
        for (int kk = 0; kk < 16; kk++) {
            float4 a4 = *(const float4*)&As[kk][ty * 4];
            float4 b4 = *(const float4*)&Bs[kk][tx * 4];
            u64 b01 = packf2(b4.x, b4.y), b23 = packf2(b4.z, b4.w);
            u64 as;
            as = packf2(a4.x, a4.x); acc2[0][0] = fmaf2(as, b01, acc2[0][0]); acc2[0][1] = fmaf2(as, b23, acc2[0][1]);
            as = packf2(a4.y, a4.y); acc2[1][0] = fmaf2(as, b01, acc2[1][0]); acc2[1][1] = fmaf2(as, b23, acc2[1][1]);
            as = packf2(a4.z, a4.z); acc2[2][0] = fmaf2(as, b01, acc2[2][0]); acc2[2][1] = fmaf2(as, b23, acc2[2][1]);
            as = packf2(a4.w, a4.w); acc2[3][0] = fmaf2(as, b01, acc2[3][0]); acc2[3][1] = fmaf2(as, b23, acc2[3][1]);
        }
        __syncthreads();
    }
    float vv[4][4];
#pragma unroll
    for (int r = 0; r < 4; r++) {
        unpackf2(acc2[r][0], vv[r][0], vv[r][1]);
        unpackf2(acc2[r][1], vv[r][2], vv[r][3]);
    }
#pragma unroll
    for (int r = 0; r < 4; r++) {
        int row = m0 + ty * 4 + r;
        if (row >= M) continue;
#pragma unroll
        for (int c = 0; c < 4; c++) {
            int col = n0 + tx * 4 + c;
            float v = vv[r][c];
            if (bias) v += __ldg(bias + col);
            if (doRelu) v = fmaxf(v, 0.f);
            C[(long long)row * ldc + col] = v;
        }
    }
}

// ---------------- protein branch precomputes ----------------
__global__ void wtrans_kernel(const float* __restrict__ convW) {
    int i = blockIdx.x * 256 + threadIdx.x;
    if (i < SEQL * 256) {
        int c = i >> 8, ok = i & 255, o = ok >> 3, k = ok & 7;
        g_Wt[i] = convW[o * 8000 + c * 8 + k];
    }
}

__global__ __launch_bounds__(256) void g_kernel(const float* __restrict__ emb,
                                                const float* __restrict__ Fw) {
    __shared__ float2 sEp[13 * 128];
    int o = blockIdx.x, jq = blockIdx.y;
    int t = threadIdx.x;
    for (int i = t; i < 13 * 128; i += 256) {
        int v2 = i >> 7, idx = i & 127;
        sEp[i] = make_float2(emb[(2 * v2) * 128 + idx], emb[(2 * v2 + 1) * 128 + idx]);
    }
    __syncthreads();
    int jl = t & 31, k = t >> 5;
    int j = jq * 32 + jl;
    u64 acc[13];
#pragma unroll
    for (int v2 = 0; v2 < 13; v2++) acc[v2] = 0ull;
    const float* fp = Fw + (long long)(o * 121) * 128 + j;
    const u64* eb = (const u64*)sEp;
#pragma unroll 2
    for (int l = 0; l < 121; l++) {
        float f = __ldg(fp + l * 128);
        u64 fs = packf2(f, f);
        const u64* ep = eb + (l + k);
#pragma unroll
        for (int v2 = 0; v2 < 13; v2++) acc[v2] = fmaf2(ep[v2 * 128], fs, acc[v2]);
    }
    float* gp = g_G + (long long)(o * 8 + k) * (NVOC * 128) + j;
#pragma unroll
    for (int v2 = 0; v2 < 13; v2++) {
        float lo, hi; unpackf2(acc[v2], lo, hi);
        gp[(2 * v2) * 128] = lo;
        gp[(2 * v2 + 1) * 128] = hi;
    }
}

__global__ void cb_kernel(const float* __restrict__ Fw, const float* __restrict__ convb,
                          const float* __restrict__ fcxt_b) {
    int j = blockIdx.x, o = threadIdx.x;
    float fs = 0.f;
    for (int l = 0; l < 121; l++) fs += __ldg(&Fw[(long long)(o * 121 + l) * 128 + j]);
    float a = __ldg(convb + o) * fs;
#pragma unroll
    for (int off = 16; off; off >>= 1) a += __shfl_down_sync(0xffffffffu, a, off);
    if (o == 0) g_cb[j] = __ldg(fcxt_b + j) + a;
}

__global__ __launch_bounds__(256) void ttrans_kernel(const int* __restrict__ target) {
    __shared__ int tile[32][33];
    int c0 = blockIdx.x * 32, b0 = blockIdx.y * 32;
    int tx = threadIdx.x & 31, ty = threadIdx.x >> 5;
#pragma unroll
    for (int r = 0; r < 4; r++) {
        int b = b0 + ty + r * 8;
        int c = c0 + tx;
        tile[ty + r * 8][tx] = (c < SEQL) ? __ldg(target + (long long)b * SEQL + c) : 0;
    }
    __syncthreads();
#pragma unroll
    for (int r = 0; r < 4; r++) {
        int c = c0 + ty + r * 8;
        int b = b0 + tx;
        if (c < SEQL) g_tT[c * BB + b] = tile[tx][ty + r * 8];
    }
}

__global__ __launch_bounds__(512) void xt_kernel() {
    __shared__ float4 sH4[NVOC * 4];
    __shared__ int tv[BB];
    int jc = blockIdx.x, cc = blockIdx.y;
    int t = threadIdx.x;
    int jq = t & 3, bg = t >> 2;
    u64 acc2[8][2];
#pragma unroll
    for (int i = 0; i < 8; i++) { acc2[i][0] = 0ull; acc2[i][1] = 0ull; }
    for (int c = cc * 50; c < cc * 50 + 50; c++) {
        if (t < NVOC * 4) {
            int v = t >> 2, q = t & 3;
            sH4[t] = *(const float4*)&g_H[((long long)c * NVOC + v) * 128 + jc * 16 + q * 4];
        }
        tv[t] = g_tT[c * BB + t];
        if (t < 512) tv[t + 512] = g_tT[c * BB + t + 512];
        __syncthreads();
#pragma unroll
        for (int bi = 0; bi < 8; bi++) {
            int v = tv[bi * 128 + bg];
            const u64* hp = (const u64*)&sH4[v * 4 + jq];
            acc2[bi][0] = addf2(acc2[bi][0], hp[0]);
            acc2[bi][1] = addf2(acc2[bi][1], hp[1]);
        }
        __syncthreads();
    }
    if (cc == 0) {
        float4 cb4 = *(const float4*)&g_cb[jc * 16 + jq * 4];
        u64 c01 = packf2(cb4.x, cb4.y), c23 = packf2(cb4.z, cb4.w);
#pragma unroll
        for (int bi = 0; bi < 8; bi++) {
            acc2[bi][0] = addf2(acc2[bi][0], c01);
            acc2[bi][1] = addf2(acc2[bi][1], c23);
        }
    }
#pragma unroll
    for (int bi = 0; bi < 8; bi++) {
        int b = bi * 128 + bg;
        float v0, v1, v2, v3;
        unpackf2(acc2[bi][0], v0, v1);
        unpackf2(acc2[bi][1], v2, v3);
        float* dst = &g_xc[b * 256 + 128 + jc * 16 + jq * 4];
        atomicAdd(dst + 0, v0); atomicAdd(dst + 1, v1);
        atomicAdd(dst + 2, v2); atomicAdd(dst + 3, v3);
    }
}

__global__ void out_kernel(const float* __restrict__ W, const float* __restrict__ b,
                           float* __restrict__ out) {
    int row = blockIdx.x * 8 + (threadIdx.x >> 5);
    int lane = threadIdx.x & 31;
    if (row >= BB) return;
    float acc = 0.f;
    for (int i = lane; i < 256; i += 32) acc += g_t2[row * 256 + i] * __ldg(W + i);
#pragma unroll
    for (int off = 16; off; off >>= 1) acc += __shfl_down_sync(0xffffffffu, acc, off);
    if (lane == 0) out[row] = acc + __ldg(b);
}

// ---------------- launch (forked capture: graph branch || protein branch) ----------
extern "C" void kernel_launch(void* const* d_in, const int* in_sizes, int n_in,
                              void* d_out, int out_size) {
    const float* x      = (const float*)d_in[0];
    const int*   ei     = (const int*)d_in[1];
    const int*   src    = ei;
    const int*   dst    = ei + NE;
    const int*   batch  = (const int*)d_in[2];
    const int*   target = (const int*)d_in[3];
    const float* W1a = (const float*)d_in[4];
    const float* b1a = (const float*)d_in[5];
    const float* W2a = (const float*)d_in[6];
    const float* b2a = (const float*)d_in[7];
    const float* g1  = (const float*)d_in[8];
    const float* be1 = (const float*)d_in[9];
    const float* Ws1 = (const float*)d_in[10];
    const float* bs1 = (const float*)d_in[11];
    const float* Ws2 = (const float*)d_in[12];
    const float* bs2 = (const float*)d_in[13];
    const float* gs  = (const float*)d_in[14];
    const float* bes = (const float*)d_in[15];
    const float* fc1xd_W = (const float*)d_in[16];
    const float* fc1xd_b = (const float*)d_in[17];
    const float* emb     = (const float*)d_in[18];
    const float* convW   = (const float*)d_in[19];
    const float* convb   = (const float*)d_in[20];
    const float* fcxt_W  = (const float*)d_in[21];
    const float* fcxt_b  = (const float*)d_in[22];
    const float* fc1_W   = (const float*)d_in[23];
    const float* fc1_b   = (const float*)d_in[24];
    const float* fc2_W   = (const float*)d_in[25];
    const float* fc2_b   = (const float*)d_in[26];
    const float* out_W   = (const float*)d_in[27];
    const float* out_b   = (const float*)d_in[28];

    float *p_h, *p_agg, *p_pooled, *p_xc, *p_t1, *p_t2, *p_Wt, *p_G, *p_H;
    cudaGetSymbolAddress((void**)&p_h, g_h);
    cudaGetSymbolAddress((void**)&p_agg, g_agg);
    cudaGetSymbolAddress((void**)&p_pooled, g_pooled);
    cudaGetSymbolAddress((void**)&p_xc, g_xc);
    cudaGetSymbolAddress((void**)&p_t1, g_t1);
    cudaGetSymbolAddress((void**)&p_t2, g_t2);
    cudaGetSymbolAddress((void**)&p_Wt, g_Wt);
    cudaGetSymbolAddress((void**)&p_G, g_G);
    cudaGetSymbolAddress((void**)&p_H, g_H);

    // persistent side streams/events (host objects only; graph is identical per call)
    static cudaStream_t s_prot = nullptr, s_proj = nullptr;
    static cudaEvent_t e_zero = nullptr, e_prot = nullptr, e_proj = nullptr;
    if (!s_prot) {
        cudaStreamCreateWithFlags(&s_prot, cudaStreamNonBlocking);
        cudaStreamCreateWithFlags(&s_proj, cudaStreamNonBlocking);
        cudaEventCreateWithFlags(&e_zero, cudaEventDisableTiming);
        cudaEventCreateWithFlags(&e_prot, cudaEventDisableTiming);
        cudaEventCreateWithFlags(&e_proj, cudaEventDisableTiming);
    }
    cudaStream_t s0 = (cudaStream_t)0;   // default (capture) stream

    const int EDGE_BLOCKS = (NE + 255) / 256;       // 7813
    const int AGG_BLOCKS  = (NN * 8 + 255) / 256;   // 6250
    const int PROJ_BLOCKS = (NN + PM - 1) / PM;     // 2084
    const int NP_BLOCKS   = (NN + 127) / 128;       // 1563

    // main: init (zeros deg/pooled/xc-xt/ctr), then fork
    zero_kernel<<<NBLK, 256>>>();
    cudaEventRecord(e_zero, s0);
    cudaStreamWaitEvent(s_prot, e_zero, 0);
    cudaStreamWaitEvent(s_proj, e_zero, 0);

    // side stream A: protein branch (fully independent of graph)
    wtrans_kernel<<<(SEQL * 256 + 255) / 256, 256, 0, s_prot>>>(convW);
    g_kernel<<<dim3(32, 4), 256, 0, s_prot>>>(emb, fcxt_W);
    cb_kernel<<<128, 32, 0, s_prot>>>(fcxt_W, convb, fcxt_b);
    ttrans_kernel<<<dim3((SEQL + 31) / 32, BB / 32), 256, 0, s_prot>>>(target);
    gemm64_kernel<<<dim3((NVOC * 128) / 64, (SEQL + 63) / 64), 256, 0, s_prot>>>(
        p_Wt, p_G, nullptr, p_H, SEQL, NVOC * 128, 256, NVOC * 128, 0);
    xt_kernel<<<dim3(8, 20), 512, 0, s_prot>>>();
    cudaEventRecord(e_prot, s_prot);

    // side stream B: layer-1 projection (independent of fill)
    proj_kernel<<<PROJ_BLOCKS, 192, 0, s_proj>>>(x, W1a, p_h);
    cudaEventRecord(e_proj, s_proj);

    // main: adjacency fill (needs zero), then join proj, then graph layers
    fill_kernel<<<EDGE_BLOCKS, 256>>>(src, dst);
    cudaStreamWaitEvent(s0, e_proj, 0);

    agg_kernel<<<AGG_BLOCKS, 256>>>(p_h, p_agg, 0);
    nodepass_kernel<<<NP_BLOCKS, 256>>>(p_agg, p_h, nullptr, b1a, W2a, b2a, g1, be1);
    for (int i = 0; i < 4; i++) {
        agg_kernel<<<AGG_BLOCKS, 256>>>(p_h, p_agg, 1);
        nodepass_kernel<<<NP_BLOCKS, 256>>>(p_agg, p_h, Ws1 + i * 1024, bs1 + i * 32,
                                            Ws2 + i * 1024, bs2 + i * 32,
                                            gs + i * 32, bes + i * 32);
    }

    // pooling + drug head (xc[:, :128]; xt writes xc[:, 128:] concurrently — disjoint)
    pool_kernel<<<NBLK, 256>>>(p_h, batch);
    gemm64_kernel<<<dim3(128 / 64, BB / 64), 256>>>(p_pooled, fc1xd_W, fc1xd_b,
                                                    p_xc, BB, 128, 32, 256, 1);

    // join protein branch, then joint head
    cudaStreamWaitEvent(s0, e_prot, 0);
    gemm64_kernel<<<dim3(1024 / 64, BB / 64), 256>>>(p_xc, fc1_W, fc1_b, p_t1, BB, 1024, 256, 1024, 1);
    gemm64_kernel<<<dim3(256 / 64, BB / 64), 256>>>(p_t1, fc2_W, fc2_b, p_t2, BB, 256, 1024, 256, 1);
    out_kernel<<<BB / 8, 256>>>(out_W, out_b, (float*)d_out);
}

// round 11
// speedup vs baseline: 1.8971x; 1.1630x over previous
#include <cuda_runtime.h>

#define NN 200000
#define NE 2000000
#define BB 1024
#define SEQL 1000
#define NVOC 26
#define PAD 48
#define NBLK ((NN + 255) / 256)   // 782

typedef unsigned long long u64;
__device__ __forceinline__ u64 packf2(float lo, float hi) {
    u64 d; asm("mov.b64 %0, {%1,%2};" : "=l"(d) : "f"(lo), "f"(hi)); return d;
}
__device__ __forceinline__ void unpackf2(u64 s, float& lo, float& hi) {
    asm("mov.b64 {%0,%1}, %2;" : "=f"(lo), "=f"(hi) : "l"(s));
}
__device__ __forceinline__ u64 fmaf2(u64 a, u64 b, u64 c) {
    u64 d; asm("fma.rn.f32x2 %0, %1, %2, %3;" : "=l"(d) : "l"(a), "l"(b), "l"(c)); return d;
}
__device__ __forceinline__ u64 addf2(u64 a, u64 b) {
    u64 d; asm("add.rn.f32x2 %0, %1, %2;" : "=l"(d) : "l"(a), "l"(b)); return d;
}

// ---------------- scratch (static __device__, no allocs) ----------------
__device__ float g_h[NN * 32];
__device__ float g_agg[NN * 32];
__device__ float g_sum[32];
__device__ float g_ss[32];
__device__ float g_scale[32];
__device__ float g_shift[32];
__device__ float g_pooled[BB * 32];
__device__ float g_xc[BB * 256];
__device__ float g_t1[BB * 1024];
__device__ float g_t2[BB * 256];
__device__ float g_Wt[SEQL * 256];          // convW transposed: [c][(o,k)]
__device__ float g_G[256 * NVOC * 128];     // [(o*8+k)][v*128+j]
__device__ float g_H[SEQL * NVOC * 128];    // [(c*26+v)*128+j]
__device__ float g_cb[128];
__device__ int   g_deg[NN];
__device__ int   g_colp[NN * PAD];
__device__ int   g_tT[SEQL * BB];
__device__ int   g_bcnt[BB];
__device__ int   g_ctr;

// ================= init =================
__global__ __launch_bounds__(256) void zero_kernel(const float* __restrict__ fcxt_b) {
    int i = blockIdx.x * 256 + threadIdx.x;
    if (i < NN) g_deg[i] = 0;
    if (i < BB * 32) g_pooled[i] = 0.f;
    if (i < BB * 128) {                 // zero xt region of xc (xt accumulates)
        int b = i >> 7, j = i & 127;
        g_xc[b * 256 + 128 + j] = 0.f;
    }
    if (i < 128) g_cb[i] = fcxt_b[i];   // cb accumulates on top
    if (i < BB) g_bcnt[i] = 0;
    if (i == 0) g_ctr = 0;
}

// fill padded adjacency + batch-count histogram
__global__ __launch_bounds__(256) void fill_kernel(const int* __restrict__ src,
                                                   const int* __restrict__ dst,
                                                   const int* __restrict__ batch) {
    int e = blockIdx.x * 256 + threadIdx.x;
    if (e < NN) atomicAdd(&g_bcnt[__ldg(batch + e)], 1);
    if (e < NE) {
        int d = __ldg(dst + e);
        int slot = atomicAdd(&g_deg[d], 1);
        if (slot < PAD) g_colp[d * PAD + slot] = __ldg(src + e);
    }
}

// ---------------- layer-1 projection: z = x @ W1a (tiled, coalesced, f32x2) --------
#define PM 96
#define PSTR 98
__global__ __launch_bounds__(192) void proj_kernel(const float* __restrict__ x,
                                                   const float* __restrict__ W,
                                                   float* __restrict__ h) {
    __shared__ float sX[78 * PSTR];   // transposed [f][m]
    __shared__ float sW[78 * 32];
    int t = threadIdx.x;
    for (int i = t; i < 78 * 32; i += 192) sW[i] = W[i];
    long long node0 = (long long)blockIdx.x * PM;
    for (int i = t; i < PM * 78; i += 192) {
        int m = i / 78, f = i - m * 78;
        float v = (node0 + m < NN) ? x[node0 * 78 + i] : 0.f;
        sX[f * PSTR + m] = v;
    }
    __syncthreads();
    int jg = t & 7, mg = t >> 3;      // 8 x 24
    int m0 = mg * 4, j0 = jg * 4;
    u64 acc[2][4];
#pragma unroll
    for (int c = 0; c < 4; c++) { acc[0][c] = 0ull; acc[1][c] = 0ull; }
#pragma unroll 2
    for (int f = 0; f < 78; f++) {
        float4 w4 = *(const float4*)&sW[f * 32 + j0];
        u64 a0 = *(const u64*)&sX[f * PSTR + m0];
        u64 a1 = *(const u64*)&sX[f * PSTR + m0 + 2];
        u64 w;
        w = packf2(w4.x, w4.x); acc[0][0] = fmaf2(a0, w, acc[0][0]); acc[1][0] = fmaf2(a1, w, acc[1][0]);
        w = packf2(w4.y, w4.y); acc[0][1] = fmaf2(a0, w, acc[0][1]); acc[1][1] = fmaf2(a1, w, acc[1][1]);
        w = packf2(w4.z, w4.z); acc[0][2] = fmaf2(a0, w, acc[0][2]); acc[1][2] = fmaf2(a1, w, acc[1][2]);
        w = packf2(w4.w, w4.w); acc[0][3] = fmaf2(a0, w, acc[0][3]); acc[1][3] = fmaf2(a1, w, acc[1][3]);
    }
    float v[4][4];
#pragma unroll
    for (int c = 0; c < 4; c++) {
        unpackf2(acc[0][c], v[0][c], v[1][c]);
        unpackf2(acc[1][c], v[2][c], v[3][c]);
    }
#pragma unroll
    for (int i = 0; i < 4; i++) {
        if (node0 + m0 + i < NN)
            *(float4*)&h[(node0 + m0 + i) * 32 + j0] =
                make_float4(v[i][0], v[i][1], v[i][2], v[i][3]);
    }
}

// ---------------- gather aggregation (+ fused BN affine) ----------------
__global__ __launch_bounds__(256) void agg_kernel(const float* __restrict__ h,
                                                  float* __restrict__ agg, int useNorm) {
    if (blockIdx.x == 0 && threadIdx.x < 64) {
        if (threadIdx.x < 32) g_sum[threadIdx.x] = 0.f;
        else g_ss[threadIdx.x - 32] = 0.f;
    }
    int gid = blockIdx.x * 256 + threadIdx.x;
    int node = gid >> 3, q = gid & 7;
    if (node >= NN) return;
    int deg = __ldg(&g_deg[node]);
    if (deg > PAD) deg = PAD;
    const int* cp = g_colp + node * PAD;
    float4 acc = __ldg((const float4*)(h + node * 32) + q);
    int s = 0;
    for (; s + 3 < deg; s += 4) {
        int n1 = __ldg(cp + s), n2 = __ldg(cp + s + 1);
        int n3 = __ldg(cp + s + 2), n4 = __ldg(cp + s + 3);
        float4 v1 = __ldg((const float4*)(h + n1 * 32) + q);
        float4 v2 = __ldg((const float4*)(h + n2 * 32) + q);
        float4 v3 = __ldg((const float4*)(h + n3 * 32) + q);
        float4 v4 = __ldg((const float4*)(h + n4 * 32) + q);
        acc.x += (v1.x + v2.x) + (v3.x + v4.x);
        acc.y += (v1.y + v2.y) + (v3.y + v4.y);
        acc.z += (v1.z + v2.z) + (v3.z + v4.z);
        acc.w += (v1.w + v2.w) + (v3.w + v4.w);
    }
    for (; s < deg; s++) {
        int n1 = __ldg(cp + s);
        float4 v1 = __ldg((const float4*)(h + n1 * 32) + q);
        acc.x += v1.x; acc.y += v1.y; acc.z += v1.z; acc.w += v1.w;
    }
    if (useNorm) {
        float4 sc = ((const float4*)g_scale)[q];
        float4 sh = ((const float4*)g_shift)[q];
        float cnt = (float)(deg + 1);
        acc.x = sc.x * acc.x + cnt * sh.x;
        acc.y = sc.y * acc.y + cnt * sh.y;
        acc.z = sc.z * acc.z + cnt * sh.z;
        acc.w = sc.w * acc.w + cnt * sh.w;
    }
    ((float4*)(agg + node * 32))[q] = acc;
}

// ---------------- per-node GIN MLP + relu + fused BN stats & finalize (+pool) ------
__global__ __launch_bounds__(256) void nodepass_kernel(const float* __restrict__ agg,
                                                       float* __restrict__ hout,
                                                       const float* __restrict__ W1,
                                                       const float* __restrict__ b1,
                                                       const float* __restrict__ W2,
                                                       const float* __restrict__ b2,
                                                       const float* __restrict__ gamma,
                                                       const float* __restrict__ beta,
                                                       const int* __restrict__ batch,
                                                       int doPool) {
    __shared__ float sT[32 * 130];
    __shared__ float sW1[1024], sW2[1024], sb1[32], sb2[32];
    __shared__ int isLast;
    int t = threadIdx.x;
    if (W1) { for (int i = t; i < 1024; i += 256) sW1[i] = W1[i]; }
    else    { for (int i = t; i < 1024; i += 256) sW1[i] = ((i >> 5) == (i & 31)) ? 1.f : 0.f; }
    for (int i = t; i < 1024; i += 256) sW2[i] = W2[i];
    if (t < 32) { sb1[t] = b1[t]; sb2[t] = b2[t]; }
    long long node0 = (long long)blockIdx.x * 128;
#pragma unroll
    for (int r = 0; r < 4; r++) {
        int fidx = r * 1024 + t * 4;
        int m = fidx >> 5, f = fidx & 31;
        float4 v = make_float4(0.f, 0.f, 0.f, 0.f);
        if (node0 + m < NN) v = *(const float4*)(agg + (node0 + m) * 32 + f);
        sT[f * 130 + m] = v.x; sT[(f + 1) * 130 + m] = v.y;
        sT[(f + 2) * 130 + m] = v.z; sT[(f + 3) * 130 + m] = v.w;
    }
    __syncthreads();
    int jg = t & 7, mg = t >> 3;
    int m0 = mg * 4, j0 = jg * 4;
    u64 acc[2][4];
#pragma unroll
    for (int c = 0; c < 4; c++) { float bb = sb1[j0 + c]; acc[0][c] = packf2(bb, bb); acc[1][c] = acc[0][c]; }
#pragma unroll
    for (int f = 0; f < 32; f++) {
        float4 w4 = *(const float4*)&sW1[f * 32 + j0];
        u64 a0 = *(const u64*)&sT[f * 130 + m0];
        u64 a1 = *(const u64*)&sT[f * 130 + m0 + 2];
        u64 w;
        w = packf2(w4.x, w4.x); acc[0][0] = fmaf2(a0, w, acc[0][0]); acc[1][0] = fmaf2(a1, w, acc[1][0]);
        w = packf2(w4.y, w4.y); acc[0][1] = fmaf2(a0, w, acc[0][1]); acc[1][1] = fmaf2(a1, w, acc[1][1]);
        w = packf2(w4.z, w4.z); acc[0][2] = fmaf2(a0, w, acc[0][2]); acc[1][2] = fmaf2(a1, w, acc[1][2]);
        w = packf2(w4.w, w4.w); acc[0][3] = fmaf2(a0, w, acc[0][3]); acc[1][3] = fmaf2(a1, w, acc[1][3]);
    }
    __syncthreads();
#pragma unroll
    for (int c = 0; c < 4; c++) {
        float x0, x1, x2, x3;
        unpackf2(acc[0][c], x0, x1); unpackf2(acc[1][c], x2, x3);
        x0 = fmaxf(x0, 0.f); x1 = fmaxf(x1, 0.f); x2 = fmaxf(x2, 0.f); x3 = fmaxf(x3, 0.f);
        *(u64*)&sT[(j0 + c) * 130 + m0]     = packf2(x0, x1);
        *(u64*)&sT[(j0 + c) * 130 + m0 + 2] = packf2(x2, x3);
    }
    __syncthreads();
#pragma unroll
    for (int c = 0; c < 4; c++) { float bb = sb2[j0 + c]; acc[0][c] = packf2(bb, bb); acc[1][c] = acc[0][c]; }
#pragma unroll
    for (int f = 0; f < 32; f++) {
        float4 w4 = *(const float4*)&sW2[f * 32 + j0];
        u64 a0 = *(const u64*)&sT[f * 130 + m0];
        u64 a1 = *(const u64*)&sT[f * 130 + m0 + 2];
        u64 w;
        w = packf2(w4.x, w4.x); acc[0][0] = fmaf2(a0, w, acc[0][0]); acc[1][0] = fmaf2(a1, w, acc[1][0]);
        w = packf2(w4.y, w4.y); acc[0][1] = fmaf2(a0, w, acc[0][1]); acc[1][1] = fmaf2(a1, w, acc[1][1]);
        w = packf2(w4.z, w4.z); acc[0][2] = fmaf2(a0, w, acc[0][2]); acc[1][2] = fmaf2(a1, w, acc[1][2]);
        w = packf2(w4.w, w4.w); acc[0][3] = fmaf2(a0, w, acc[0][3]); acc[1][3] = fmaf2(a1, w, acc[1][3]);
    }
    float v[4][4];
#pragma unroll
    for (int c = 0; c < 4; c++) {
        unpackf2(acc[0][c], v[0][c], v[1][c]);
        unpackf2(acc[1][c], v[2][c], v[3][c]);
    }
    float ls[4] = {0.f, 0.f, 0.f, 0.f}, lq[4] = {0.f, 0.f, 0.f, 0.f};
#pragma unroll
    for (int i = 0; i < 4; i++) {
        bool ok = (node0 + m0 + i < NN);
        float r0 = fmaxf(v[i][0], 0.f), r1 = fmaxf(v[i][1], 0.f);
        float r2 = fmaxf(v[i][2], 0.f), r3 = fmaxf(v[i][3], 0.f);
        if (ok) {
            *(float4*)&hout[(node0 + m0 + i) * 32 + j0] = make_float4(r0, r1, r2, r3);
            ls[0] += r0; ls[1] += r1; ls[2] += r2; ls[3] += r3;
            lq[0] += r0 * r0; lq[1] += r1 * r1; lq[2] += r2 * r2; lq[3] += r3 * r3;
            if (doPool) {
                int b = __ldg(batch + node0 + m0 + i);
                float* pr = g_pooled + b * 32 + j0;
                atomicAdd(pr + 0, r0); atomicAdd(pr + 1, r1);
                atomicAdd(pr + 2, r2); atomicAdd(pr + 3, r3);
            }
        }
    }
    __syncthreads();
    float* sS = sT;
    float* sQ = sT + 32 * 33;
#pragma unroll
    for (int c = 0; c < 4; c++) {
        sS[mg * 33 + j0 + c] = ls[c];
        sQ[mg * 33 + j0 + c] = lq[c];
    }
    __syncthreads();
    if (t < 32) {
        float a = 0.f, b = 0.f;
#pragma unroll
        for (int r = 0; r < 32; r++) { a += sS[r * 33 + t]; b += sQ[r * 33 + t]; }
        atomicAdd(&g_sum[t], a);
        atomicAdd(&g_ss[t], b);
    }
    __threadfence();
    if (t == 0) isLast = (atomicAdd(&g_ctr, 1) == (int)gridDim.x - 1);
    __syncthreads();
    if (isLast) {
        if (t < 32) {
            float m = g_sum[t] * (1.0f / (float)NN);
            float var = g_ss[t] * (1.0f / (float)NN) - m * m;
            float sc = __ldg(gamma + t) * rsqrtf(var + 1e-5f);
            g_scale[t] = sc;
            g_shift[t] = __ldg(beta + t) - m * sc;
        }
        if (t == 32) g_ctr = 0;
    }
}

// ---------------- pool affine fixup: pooled = sc*raw + cnt*sh ----------------
__global__ __launch_bounds__(256) void poolfix_kernel() {
    int i = blockIdx.x * 256 + threadIdx.x;
    if (i < BB * 32) {
        int b = i >> 5, j = i & 31;
        g_pooled[i] = g_scale[j] * g_pooled[i] + (float)g_bcnt[b] * g_shift[j];
    }
}

// ---------------- generic tiled GEMM (f32x2 inner) ----------------
__global__ __launch_bounds__(256) void gemm64_kernel(const float* __restrict__ A,
                                                     const float* __restrict__ B,
                                                     const float* __restrict__ bias,
                                                     float* __restrict__ C,
                                                     int M, int N, int K, int ldc, int doRelu) {
    __shared__ float As[16][68];
    __shared__ float Bs[16][68];
    int tx = threadIdx.x & 15, ty = threadIdx.x >> 4;
    int m0 = blockIdx.y * 64, n0 = blockIdx.x * 64;
    int la_m = threadIdx.x >> 2;
    int la_k = (threadIdx.x & 3) * 4;
    int lb_k = threadIdx.x >> 4;
    int lb_n = (threadIdx.x & 15) * 4;
    u64 acc2[4][2];
#pragma unroll
    for (int r = 0; r < 4; r++) { acc2[r][0] = 0ull; acc2[r][1] = 0ull; }

    for (int k0 = 0; k0 < K; k0 += 16) {
        float4 av = make_float4(0.f, 0.f, 0.f, 0.f);
        if (m0 + la_m < M) av = *(const float4*)(A + (long long)(m0 + la_m) * K + k0 + la_k);
        As[la_k + 0][la_m] = av.x; As[la_k + 1][la_m] = av.y;
        As[la_k + 2][la_m] = av.z; As[la_k + 3][la_m] = av.w;
        float4 bv = *(const float4*)(B + (long long)(k0 + lb_k) * N + n0 + lb_n);
        *(float4*)&Bs[lb_k][lb_n] = bv;
        __syncthreads();
#pragma unroll
        for (int kk = 0; kk < 16; kk++) {
            float4 a4 = *(const float4*)&As[kk][ty * 4];
            float4 b4 = *(const float4*)&Bs[kk][tx * 4];
            u64 b01 = packf2(b4.x, b4.y), b23 = packf2(b4.z, b4.w);
            u64 as;
            as = packf2(a4.x, a4.x); acc2[0][0] = fmaf2(as, b01, acc2[0][0]); acc2[0][1] = fmaf2(as, b23, acc2[0][1]);
            as = packf2(a4.y, a4.y); acc2[1][0] = fmaf2(as, b01, acc2[1][0]); acc2[1][1] = fmaf2(as, b23, acc2[1][1]);
            as = packf2(a4.z, a4.z); acc2[2][0] = fmaf2(as, b01, acc2[2][0]); acc2[2][1] = fmaf2(as, b23, acc2[2][1]);
            as = packf2(a4.w, a4.w); acc2[3][0] = fmaf2(as, b01, acc2[3][0]); acc2[3][1] = fmaf2(as, b23, acc2[3][1]);
        }
        __syncthreads();
    }
    float vv[4][4];
#pragma unroll
    for (int r = 0; r < 4; r++) {
        unpackf2(acc2[r][0], vv[r][0], vv[r][1]);
        unpackf2(acc2[r][1], vv[r][2], vv[r][3]);
    }
#pragma unroll
    for (int r = 0; r < 4; r++) {
        int row = m0 + ty * 4 + r;
        if (row >= M) continue;
#pragma unroll
        for (int c = 0; c < 4; c++) {
            int col = n0 + tx * 4 + c;
            float v = vv[r][c];
            if (bias) v += __ldg(bias + col);
            if (doRelu) v = fmaxf(v, 0.f);
            C[(long long)row * ldc + col] = v;
        }
    }
}

// ---------------- protein branch precomputes ----------------
__global__ void wtrans_kernel(const float* __restrict__ convW) {
    int i = blockIdx.x * 256 + threadIdx.x;
    if (i < SEQL * 256) {
        int c = i >> 8, ok = i & 255, o = ok >> 3, k = ok & 7;
        g_Wt[i] = convW[o * 8000 + c * 8 + k];
    }
}

__global__ __launch_bounds__(256) void g_kernel(const float* __restrict__ emb,
                                                const float* __restrict__ Fw) {
    __shared__ float2 sEp[13 * 128];
    int o = blockIdx.x, jq = blockIdx.y;
    int t = threadIdx.x;
    for (int i = t; i < 13 * 128; i += 256) {
        int v2 = i >> 7, idx = i & 127;
        sEp[i] = make_float2(emb[(2 * v2) * 128 + idx], emb[(2 * v2 + 1) * 128 + idx]);
    }
    __syncthreads();
    int jl = t & 31, k = t >> 5;
    int j = jq * 32 + jl;
    u64 acc[13];
#pragma unroll
    for (int v2 = 0; v2 < 13; v2++) acc[v2] = 0ull;
    const float* fp = Fw + (long long)(o * 121) * 128 + j;
    const u64* eb = (const u64*)sEp;
#pragma unroll 2
    for (int l = 0; l < 121; l++) {
        float f = __ldg(fp + l * 128);
        u64 fs = packf2(f, f);
        const u64* ep = eb + (l + k);
#pragma unroll
        for (int v2 = 0; v2 < 13; v2++) acc[v2] = fmaf2(ep[v2 * 128], fs, acc[v2]);
    }
    float* gp = g_G + (long long)(o * 8 + k) * (NVOC * 128) + j;
#pragma unroll
    for (int v2 = 0; v2 < 13; v2++) {
        float lo, hi; unpackf2(acc[v2], lo, hi);
        gp[(2 * v2) * 128] = lo;
        gp[(2 * v2 + 1) * 128] = hi;
    }
}

// cb accumulate: grid 32 (o), block 128 (j); coalesced row loads, atomic combine
__global__ __launch_bounds__(128) void cb_kernel(const float* __restrict__ Fw,
                                                 const float* __restrict__ convb) {
    int o = blockIdx.x, j = threadIdx.x;
    float cbo = __ldg(convb + o);
    const float* fp = Fw + (long long)(o * 121) * 128 + j;
    float acc = 0.f;
#pragma unroll 4
    for (int l = 0; l < 121; l++) acc += __ldg(fp + l * 128);
    atomicAdd(&g_cb[j], acc * cbo);
}

__global__ __launch_bounds__(256) void ttrans_kernel(const int* __restrict__ target) {
    __shared__ int tile[32][33];
    int c0 = blockIdx.x * 32, b0 = blockIdx.y * 32;
    int tx = threadIdx.x & 31, ty = threadIdx.x >> 5;
#pragma unroll
    for (int r = 0; r < 4; r++) {
        int b = b0 + ty + r * 8;
        int c = c0 + tx;
        tile[ty + r * 8][tx] = (c < SEQL) ? __ldg(target + (long long)b * SEQL + c) : 0;
    }
    __syncthreads();
#pragma unroll
    for (int r = 0; r < 4; r++) {
        int c = c0 + ty + r * 8;
        int b = b0 + tx;
        if (c < SEQL) g_tT[c * BB + b] = tile[tx][ty + r * 8];
    }
}

__global__ __launch_bounds__(512) void xt_kernel() {
    __shared__ float4 sH4[NVOC * 4];
    __shared__ int tv[BB];
    int jc = blockIdx.x, cc = blockIdx.y;
    int t = threadIdx.x;
    int jq = t & 3, bg = t >> 2;
    u64 acc2[8][2];
#pragma unroll
    for (int i = 0; i < 8; i++) { acc2[i][0] = 0ull; acc2[i][1] = 0ull; }
    for (int c = cc * 50; c < cc * 50 + 50; c++) {
        if (t < NVOC * 4) {
            int v = t >> 2, q = t & 3;
            sH4[t] = *(const float4*)&g_H[((long long)c * NVOC + v) * 128 + jc * 16 + q * 4];
        }
        tv[t] = g_tT[c * BB + t];
        if (t < 512) tv[t + 512] = g_tT[c * BB + t + 512];
        __syncthreads();
#pragma unroll
        for (int bi = 0; bi < 8; bi++) {
            int v = tv[bi * 128 + bg];
            const u64* hp = (const u64*)&sH4[v * 4 + jq];
            acc2[bi][0] = addf2(acc2[bi][0], hp[0]);
            acc2[bi][1] = addf2(acc2[bi][1], hp[1]);
        }
        __syncthreads();
    }
    if (cc == 0) {
        float4 cb4 = *(const float4*)&g_cb[jc * 16 + jq * 4];
        u64 c01 = packf2(cb4.x, cb4.y), c23 = packf2(cb4.z, cb4.w);
#pragma unroll
        for (int bi = 0; bi < 8; bi++) {
            acc2[bi][0] = addf2(acc2[bi][0], c01);
            acc2[bi][1] = addf2(acc2[bi][1], c23);
        }
    }
#pragma unroll
    for (int bi = 0; bi < 8; bi++) {
        int b = bi * 128 + bg;
        float v0, v1, v2, v3;
        unpackf2(acc2[bi][0], v0, v1);
        unpackf2(acc2[bi][1], v2, v3);
        float* dst = &g_xc[b * 256 + 128 + jc * 16 + jq * 4];
        atomicAdd(dst + 0, v0); atomicAdd(dst + 1, v1);
        atomicAdd(dst + 2, v2); atomicAdd(dst + 3, v3);
    }
}

__global__ void out_kernel(const float* __restrict__ W, const float* __restrict__ b,
                           float* __restrict__ out) {
    int row = blockIdx.x * 8 + (threadIdx.x >> 5);
    int lane = threadIdx.x & 31;
    if (row >= BB) return;
    float acc = 0.f;
    for (int i = lane; i < 256; i += 32) acc += g_t2[row * 256 + i] * __ldg(W + i);
#pragma unroll
    for (int off = 16; off; off >>= 1) acc += __shfl_down_sync(0xffffffffu, acc, off);
    if (lane == 0) out[row] = acc + __ldg(b);
}

// ---------------- launch (fork AFTER zero's event — capture-legal topology) --------
extern "C" void kernel_launch(void* const* d_in, const int* in_sizes, int n_in,
                              void* d_out, int out_size) {
    const float* x      = (const float*)d_in[0];
    const int*   ei     = (const int*)d_in[1];
    const int*   src    = ei;
    const int*   dst    = ei + NE;
    const int*   batch  = (const int*)d_in[2];
    const int*   target = (const int*)d_in[3];
    const float* W1a = (const float*)d_in[4];
    const float* b1a = (const float*)d_in[5];
    const float* W2a = (const float*)d_in[6];
    const float* b2a = (const float*)d_in[7];
    const float* g1  = (const float*)d_in[8];
    const float* be1 = (const float*)d_in[9];
    const float* Ws1 = (const float*)d_in[10];
    const float* bs1 = (const float*)d_in[11];
    const float* Ws2 = (const float*)d_in[12];
    const float* bs2 = (const float*)d_in[13];
    const float* gs  = (const float*)d_in[14];
    const float* bes = (const float*)d_in[15];
    const float* fc1xd_W = (const float*)d_in[16];
    const float* fc1xd_b = (const float*)d_in[17];
    const float* emb     = (const float*)d_in[18];
    const float* convW   = (const float*)d_in[19];
    const float* convb   = (const float*)d_in[20];
    const float* fcxt_W  = (const float*)d_in[21];
    const float* fcxt_b  = (const float*)d_in[22];
    const float* fc1_W   = (const float*)d_in[23];
    const float* fc1_b   = (const float*)d_in[24];
    const float* fc2_W   = (const float*)d_in[25];
    const float* fc2_b   = (const float*)d_in[26];
    const float* out_W   = (const float*)d_in[27];
    const float* out_b   = (const float*)d_in[28];

    float *p_h, *p_agg, *p_pooled, *p_xc, *p_t1, *p_t2, *p_Wt, *p_G, *p_H;
    cudaGetSymbolAddress((void**)&p_h, g_h);
    cudaGetSymbolAddress((void**)&p_agg, g_agg);
    cudaGetSymbolAddress((void**)&p_pooled, g_pooled);
    cudaGetSymbolAddress((void**)&p_xc, g_xc);
    cudaGetSymbolAddress((void**)&p_t1, g_t1);
    cudaGetSymbolAddress((void**)&p_t2, g_t2);
    cudaGetSymbolAddress((void**)&p_Wt, g_Wt);
    cudaGetSymbolAddress((void**)&p_G, g_G);
    cudaGetSymbolAddress((void**)&p_H, g_H);

    static cudaStream_t s_prot = nullptr, s_proj = nullptr;
    static cudaEvent_t e_zero = nullptr, e_prot = nullptr, e_proj = nullptr;
    if (!s_prot) {
        cudaStreamCreateWithFlags(&s_prot, cudaStreamNonBlocking);
        cudaStreamCreateWithFlags(&s_proj, cudaStreamNonBlocking);
        cudaEventCreateWithFlags(&e_zero, cudaEventDisableTiming);
        cudaEventCreateWithFlags(&e_prot, cudaEventDisableTiming);
        cudaEventCreateWithFlags(&e_proj, cudaEventDisableTiming);
    }
    cudaStream_t s0 = (cudaStream_t)0;

    const int EDGE_BLOCKS = (NE + 255) / 256;       // 7813
    const int AGG_BLOCKS  = (NN * 8 + 255) / 256;   // 6250
    const int PROJ_BLOCKS = (NN + PM - 1) / PM;     // 2084
    const int NP_BLOCKS   = (NN + 127) / 128;       // 1563

    // main: init, then fork (side streams MUST first wait an event from s0)
    zero_kernel<<<NBLK, 256>>>(fcxt_b);
    cudaEventRecord(e_zero, s0);
    cudaStreamWaitEvent(s_prot, e_zero, 0);
    cudaStreamWaitEvent(s_proj, e_zero, 0);

    // side stream A: protein branch
    wtrans_kernel<<<(SEQL * 256 + 255) / 256, 256, 0, s_prot>>>(convW);
    g_kernel<<<dim3(32, 4), 256, 0, s_prot>>>(emb, fcxt_W);
    cb_kernel<<<32, 128, 0, s_prot>>>(fcxt_W, convb);
    ttrans_kernel<<<dim3((SEQL + 31) / 32, BB / 32), 256, 0, s_prot>>>(target);
    gemm64_kernel<<<dim3((NVOC * 128) / 64, (SEQL + 63) / 64), 256, 0, s_prot>>>(
        p_Wt, p_G, nullptr, p_H, SEQL, NVOC * 128, 256, NVOC * 128, 0);
    xt_kernel<<<dim3(8, 20), 512, 0, s_prot>>>();
    cudaEventRecord(e_prot, s_prot);

    // side stream B: layer-1 projection
    proj_kernel<<<PROJ_BLOCKS, 192, 0, s_proj>>>(x, W1a, p_h);
    cudaEventRecord(e_proj, s_proj);

    // main: adjacency fill, join proj, graph layers
    fill_kernel<<<EDGE_BLOCKS, 256>>>(src, dst, batch);
    cudaStreamWaitEvent(s0, e_proj, 0);

    agg_kernel<<<AGG_BLOCKS, 256>>>(p_h, p_agg, 0);
    nodepass_kernel<<<NP_BLOCKS, 256>>>(p_agg, p_h, nullptr, b1a, W2a, b2a, g1, be1,
                                        batch, 0);
    for (int i = 0; i < 4; i++) {
        agg_kernel<<<AGG_BLOCKS, 256>>>(p_h, p_agg, 1);
        nodepass_kernel<<<NP_BLOCKS, 256>>>(p_agg, p_h, Ws1 + i * 1024, bs1 + i * 32,
                                            Ws2 + i * 1024, bs2 + i * 32,
                                            gs + i * 32, bes + i * 32,
                                            batch, (i == 3) ? 1 : 0);
    }

    // pool affine fixup + drug head
    poolfix_kernel<<<(BB * 32 + 255) / 256, 256>>>();
    gemm64_kernel<<<dim3(128 / 64, BB / 64), 256>>>(p_pooled, fc1xd_W, fc1xd_b,
                                                    p_xc, BB, 128, 32, 256, 1);

    // join protein branch, then joint head
    cudaStreamWaitEvent(s0, e_prot, 0);
    gemm64_kernel<<<dim3(1024 / 64, BB / 64), 256>>>(p_xc, fc1_W, fc1_b, p_t1, BB, 1024, 256, 1024, 1);
    gemm64_kernel<<<dim3(256 / 64, BB / 64), 256>>>(p_t1, fc2_W, fc2_b, p_t2, BB, 256, 1024, 256, 1);
    out_kernel<<<BB / 8, 256>>>(out_W, out_b, (float*)d_out);
}